// round 1
// baseline (speedup 1.0000x reference)
#include <cuda_runtime.h>
#include <math.h>

#define BATCH 4
#define SEQ   2048
#define DIM   2048
#define NHEAD 16
#define HD    128
#define MROWS (BATCH*SEQ)   // 8192

// Scratch (static device globals: allowed; no cudaMalloc)
__device__ float g_q[(size_t)MROWS * DIM];
__device__ float g_k[(size_t)MROWS * DIM];
__device__ float g_v[(size_t)MROWS * DIM];
__device__ float g_att[(size_t)MROWS * DIM];

// ---------------------------------------------------------------------------
// GEMM: C[M,N] = A[M,K] * B[N,K]^T (+bias), all row-major. M,N,K mult of 128/16.
// 128x128 block tile, BK=16, 256 threads, 8x8 per-thread microtile.
// ---------------------------------------------------------------------------
#define GBM 128
#define GBN 128
#define GBK 16

__global__ __launch_bounds__(256, 2)
void gemm_nt_kernel(const float* __restrict__ A, const float* __restrict__ B,
                    const float* __restrict__ bias, float* __restrict__ C,
                    int M, int N, int K)
{
    __shared__ float As[GBK][GBM];
    __shared__ float Bs[GBK][GBN];

    const int tid = threadIdx.x;
    const int bm = blockIdx.y * GBM;
    const int bn = blockIdx.x * GBN;

    const int lr = tid >> 2;          // 0..63 (load row)
    const int lc = (tid & 3) << 2;    // 0,4,8,12 (load k-col, float4)
    const int tm = (tid >> 4) << 3;   // compute row base
    const int tn = (tid & 15) << 3;   // compute col base

    float acc[8][8];
#pragma unroll
    for (int i = 0; i < 8; i++)
#pragma unroll
        for (int j = 0; j < 8; j++) acc[i][j] = 0.f;

    const float* Aptr = A + (size_t)(bm + lr) * K + lc;
    const float* Bptr = B + (size_t)(bn + lr) * K + lc;

    for (int k0 = 0; k0 < K; k0 += GBK) {
        float4 a0 = *(const float4*)(Aptr + k0);
        float4 a1 = *(const float4*)(Aptr + (size_t)64 * K + k0);
        float4 b0 = *(const float4*)(Bptr + k0);
        float4 b1 = *(const float4*)(Bptr + (size_t)64 * K + k0);

        As[lc+0][lr]    = a0.x; As[lc+1][lr]    = a0.y; As[lc+2][lr]    = a0.z; As[lc+3][lr]    = a0.w;
        As[lc+0][lr+64] = a1.x; As[lc+1][lr+64] = a1.y; As[lc+2][lr+64] = a1.z; As[lc+3][lr+64] = a1.w;
        Bs[lc+0][lr]    = b0.x; Bs[lc+1][lr]    = b0.y; Bs[lc+2][lr]    = b0.z; Bs[lc+3][lr]    = b0.w;
        Bs[lc+0][lr+64] = b1.x; Bs[lc+1][lr+64] = b1.y; Bs[lc+2][lr+64] = b1.z; Bs[lc+3][lr+64] = b1.w;
        __syncthreads();

#pragma unroll
        for (int kk = 0; kk < GBK; kk++) {
            float4 x0 = *(const float4*)&As[kk][tm];
            float4 x1 = *(const float4*)&As[kk][tm+4];
            float4 y0 = *(const float4*)&Bs[kk][tn];
            float4 y1 = *(const float4*)&Bs[kk][tn+4];
            float av[8] = {x0.x,x0.y,x0.z,x0.w,x1.x,x1.y,x1.z,x1.w};
            float bv[8] = {y0.x,y0.y,y0.z,y0.w,y1.x,y1.y,y1.z,y1.w};
#pragma unroll
            for (int i = 0; i < 8; i++)
#pragma unroll
                for (int j = 0; j < 8; j++)
                    acc[i][j] += av[i] * bv[j];
        }
        __syncthreads();
    }

    float bv[8];
#pragma unroll
    for (int j = 0; j < 8; j++) bv[j] = bias ? bias[bn + tn + j] : 0.f;

#pragma unroll
    for (int i = 0; i < 8; i++) {
        float4 o0, o1;
        o0.x = acc[i][0] + bv[0]; o0.y = acc[i][1] + bv[1];
        o0.z = acc[i][2] + bv[2]; o0.w = acc[i][3] + bv[3];
        o1.x = acc[i][4] + bv[4]; o1.y = acc[i][5] + bv[5];
        o1.z = acc[i][6] + bv[6]; o1.w = acc[i][7] + bv[7];
        float* Crow = C + (size_t)(bm + tm + i) * N + bn + tn;
        *(float4*)(Crow)     = o0;
        *(float4*)(Crow + 4) = o1;
    }
}

// ---------------------------------------------------------------------------
// RoPE (in place). One thread per (b,s,h,i) pair, i in [0,64).
// ---------------------------------------------------------------------------
__global__ __launch_bounds__(256)
void rope_kernel(float* __restrict__ T)
{
    int idx = blockIdx.x * blockDim.x + threadIdx.x;
    int i = idx & 63;
    int h = (idx >> 6) & (NHEAD - 1);
    int s = (idx >> 10) & (SEQ - 1);
    int b = idx >> 21;

    // inv_freq = 10000^(-i/64) = exp(-ln(10000) * i / 64)
    float inv = expf(-9.210340371976184f * ((float)i * (1.0f / 64.0f)));
    float ang = (float)s * inv;
    float c, sn;
    sincosf(ang, &sn, &c);

    float* base = T + (size_t)(b * SEQ + s) * DIM + h * HD;
    float t1 = base[i];
    float t2 = base[i + 64];
    base[i]      = t1 * c - t2 * sn;
    base[i + 64] = t2 * c + t1 * sn;
}

// ---------------------------------------------------------------------------
// Causal flash attention, fp32. Grid: (SEQ/64, BATCH*NHEAD). 256 threads.
// Q,K in smem transposed [d][row]; V row-major [row][d]; P padded stride 65.
// ---------------------------------------------------------------------------
#define AM 64
#define AN 64
#define PS_STRIDE 65
#define ATTN_SMEM_FLOATS (128*64 + 128*64 + 64*128 + 64*PS_STRIDE + 192)
#define ATTN_SMEM_BYTES  (ATTN_SMEM_FLOATS * 4)

__global__ __launch_bounds__(256, 1)
void attn_kernel(const float* __restrict__ Q, const float* __restrict__ K,
                 const float* __restrict__ V, float* __restrict__ O)
{
    extern __shared__ float sm[];
    float* Qs    = sm;                       // [128][64] transposed
    float* Ks    = Qs + 128 * 64;            // [128][64] transposed
    float* Vs    = Ks + 128 * 64;            // [64][128] row-major
    float* Ps    = Vs + 64 * 128;            // [64][65]
    float* row_m = Ps + 64 * PS_STRIDE;
    float* row_l = row_m + 64;
    float* row_a = row_l + 64;

    const int tid = threadIdx.x;
    const int bh  = blockIdx.y;
    const int b   = bh >> 4;
    const int h   = bh & (NHEAD - 1);
    const int qt  = blockIdx.x;
    const int q0  = qt * AM;

    const float* Qb = Q + (size_t)(b * SEQ + q0) * DIM + h * HD;

    // Load Q tile transposed. r-fast mapping: lanes cover rows -> conflict-free
    // transposed smem stores (gmem slightly uncoalesced, L2-resident).
#pragma unroll
    for (int u = 0; u < 8; u++) {
        int li = u * 256 + tid;
        int r  = li & 63;
        int d4 = li >> 6;          // 0..31
        float4 t = *(const float4*)&Qb[(size_t)r * DIM + d4 * 4];
        int dd = d4 * 4;
        Qs[(dd+0)*64 + r] = t.x;
        Qs[(dd+1)*64 + r] = t.y;
        Qs[(dd+2)*64 + r] = t.z;
        Qs[(dd+3)*64 + r] = t.w;
    }
    if (tid < 64) { row_m[tid] = -1e30f; row_l[tid] = 0.f; }

    float Ot[4][8];
#pragma unroll
    for (int i = 0; i < 4; i++)
#pragma unroll
        for (int c = 0; c < 8; c++) Ot[i][c] = 0.f;

    const int ty  = tid >> 4;
    const int tx  = tid & 15;
    const int tm  = ty * 4;      // score/output row base
    const int tn  = tx * 4;      // score col base
    const int col = tx * 8;      // output col base
    const float scale = 0.08838834764831845f; // 1/sqrt(128)

    __syncthreads();

    for (int kt = 0; kt <= qt; kt++) {
        const int k0 = kt * AN;
        const float* Kb = K + (size_t)(b * SEQ + k0) * DIM + h * HD;
        const float* Vb = V + (size_t)(b * SEQ + k0) * DIM + h * HD;

#pragma unroll
        for (int u = 0; u < 8; u++) {
            int li = u * 256 + tid;
            {   // K transposed (r-fast)
                int r = li & 63, d4 = li >> 6;
                float4 t = *(const float4*)&Kb[(size_t)r * DIM + d4 * 4];
                int dd = d4 * 4;
                Ks[(dd+0)*64 + r] = t.x;
                Ks[(dd+1)*64 + r] = t.y;
                Ks[(dd+2)*64 + r] = t.z;
                Ks[(dd+3)*64 + r] = t.w;
            }
            {   // V row-major (d-fast, coalesced)
                int d4 = li & 31, r = li >> 5;
                *(float4*)&Vs[r * 128 + d4 * 4] =
                    *(const float4*)&Vb[(size_t)r * DIM + d4 * 4];
            }
        }
        __syncthreads();

        // Scores: 4x4 per thread
        float s4[4][4];
#pragma unroll
        for (int i = 0; i < 4; i++)
#pragma unroll
            for (int j = 0; j < 4; j++) s4[i][j] = 0.f;

#pragma unroll 4
        for (int d = 0; d < 128; d++) {
            float4 a  = *(const float4*)&Qs[d * 64 + tm];
            float4 bb = *(const float4*)&Ks[d * 64 + tn];
            s4[0][0] += a.x*bb.x; s4[0][1] += a.x*bb.y; s4[0][2] += a.x*bb.z; s4[0][3] += a.x*bb.w;
            s4[1][0] += a.y*bb.x; s4[1][1] += a.y*bb.y; s4[1][2] += a.y*bb.z; s4[1][3] += a.y*bb.w;
            s4[2][0] += a.z*bb.x; s4[2][1] += a.z*bb.y; s4[2][2] += a.z*bb.z; s4[2][3] += a.z*bb.w;
            s4[3][0] += a.w*bb.x; s4[3][1] += a.w*bb.y; s4[3][2] += a.w*bb.z; s4[3][3] += a.w*bb.w;
        }

        const bool diag = (kt == qt);
#pragma unroll
        for (int i = 0; i < 4; i++)
#pragma unroll
            for (int j = 0; j < 4; j++) {
                float v = s4[i][j] * scale;
                if (diag && (k0 + tn + j > q0 + tm + i)) v = -1e9f;
                Ps[(tm + i) * PS_STRIDE + tn + j] = v;
            }
        __syncthreads();

        // Online softmax update (one thread per row)
        if (tid < 64) {
            int r = tid;
            float mold = row_m[r];
            float mx = mold;
#pragma unroll 8
            for (int j = 0; j < 64; j++) mx = fmaxf(mx, Ps[r * PS_STRIDE + j]);
            float alpha = expf(mold - mx);
            float l = row_l[r] * alpha;
#pragma unroll 8
            for (int j = 0; j < 64; j++) {
                float p = expf(Ps[r * PS_STRIDE + j] - mx);
                Ps[r * PS_STRIDE + j] = p;
                l += p;
            }
            row_m[r] = mx; row_l[r] = l; row_a[r] = alpha;
        }
        __syncthreads();

        // Rescale accumulators and add P @ V
        float al[4];
#pragma unroll
        for (int i = 0; i < 4; i++) al[i] = row_a[tm + i];
#pragma unroll
        for (int i = 0; i < 4; i++)
#pragma unroll
            for (int c = 0; c < 8; c++) Ot[i][c] *= al[i];

#pragma unroll 2
        for (int j = 0; j < 64; j++) {
            float4 v0 = *(const float4*)&Vs[j * 128 + col];
            float4 v1 = *(const float4*)&Vs[j * 128 + col + 4];
#pragma unroll
            for (int i = 0; i < 4; i++) {
                float p = Ps[(tm + i) * PS_STRIDE + j];
                Ot[i][0] += p * v0.x; Ot[i][1] += p * v0.y;
                Ot[i][2] += p * v0.z; Ot[i][3] += p * v0.w;
                Ot[i][4] += p * v1.x; Ot[i][5] += p * v1.y;
                Ot[i][6] += p * v1.z; Ot[i][7] += p * v1.w;
            }
        }
        __syncthreads();
    }

    // Final normalize and write
    float* Ob = O + (size_t)(b * SEQ + q0) * DIM + h * HD;
#pragma unroll
    for (int i = 0; i < 4; i++) {
        float invl = 1.f / row_l[tm + i];
        float4 o0, o1;
        o0.x = Ot[i][0]*invl; o0.y = Ot[i][1]*invl; o0.z = Ot[i][2]*invl; o0.w = Ot[i][3]*invl;
        o1.x = Ot[i][4]*invl; o1.y = Ot[i][5]*invl; o1.z = Ot[i][6]*invl; o1.w = Ot[i][7]*invl;
        *(float4*)&Ob[(size_t)(tm + i) * DIM + col]     = o0;
        *(float4*)&Ob[(size_t)(tm + i) * DIM + col + 4] = o1;
    }
}

// ---------------------------------------------------------------------------
extern "C" void kernel_launch(void* const* d_in, const int* in_sizes, int n_in,
                              void* d_out, int out_size)
{
    (void)in_sizes; (void)n_in; (void)out_size;
    const float* x  = (const float*)d_in[0];
    const float* Wq = (const float*)d_in[1];
    const float* Wk = (const float*)d_in[2];
    const float* Wv = (const float*)d_in[3];
    const float* Wo = (const float*)d_in[4];
    const float* bo = (const float*)d_in[5];
    float* out = (float*)d_out;

    float *q, *k, *v, *att;
    cudaGetSymbolAddress((void**)&q,   g_q);
    cudaGetSymbolAddress((void**)&k,   g_k);
    cudaGetSymbolAddress((void**)&v,   g_v);
    cudaGetSymbolAddress((void**)&att, g_att);

    dim3 ggrid(DIM / GBN, MROWS / GBM);   // (16, 64)

    gemm_nt_kernel<<<ggrid, 256>>>(x, Wq, nullptr, q, MROWS, DIM, DIM);
    gemm_nt_kernel<<<ggrid, 256>>>(x, Wk, nullptr, k, MROWS, DIM, DIM);
    gemm_nt_kernel<<<ggrid, 256>>>(x, Wv, nullptr, v, MROWS, DIM, DIM);

    int rope_threads = BATCH * SEQ * NHEAD * 64;
    rope_kernel<<<rope_threads / 256, 256>>>(q);
    rope_kernel<<<rope_threads / 256, 256>>>(k);

    cudaFuncSetAttribute(attn_kernel,
                         cudaFuncAttributeMaxDynamicSharedMemorySize,
                         ATTN_SMEM_BYTES);
    attn_kernel<<<dim3(SEQ / AM, BATCH * NHEAD), 256, ATTN_SMEM_BYTES>>>(q, k, v, att);

    gemm_nt_kernel<<<ggrid, 256>>>(att, Wo, bo, out, MROWS, DIM, DIM);
}

// round 3
// speedup vs baseline: 1.5985x; 1.5985x over previous
#include <cuda_runtime.h>
#include <cuda_bf16.h>
#include <math.h>
#include <stdint.h>

#define BATCH 4
#define SEQ   2048
#define DIM   2048
#define NHEAD 16
#define HD    128
#define MROWS (BATCH*SEQ)   // 8192

// ---------------- scratch (static device globals) ----------------
__device__ float g_q[(size_t)MROWS * DIM];
__device__ float g_k[(size_t)MROWS * DIM];
__device__ float g_v[(size_t)MROWS * DIM];
__device__ float g_att[(size_t)MROWS * DIM];
__device__ __nv_bfloat16 g_xhi[(size_t)MROWS * DIM];
__device__ __nv_bfloat16 g_xlo[(size_t)MROWS * DIM];
__device__ __nv_bfloat16 g_ahi[(size_t)MROWS * DIM];
__device__ __nv_bfloat16 g_alo[(size_t)MROWS * DIM];
__device__ __nv_bfloat16 g_whi[4][(size_t)DIM * DIM];
__device__ __nv_bfloat16 g_wlo[4][(size_t)DIM * DIM];

// ---------------- low-level helpers ----------------
__device__ __forceinline__ uint32_t smem_u32(const void* p) {
    uint32_t a;
    asm("{ .reg .u64 t; cvta.to.shared.u64 t, %1; cvt.u32.u64 %0, t; }" : "=r"(a) : "l"(p));
    return a;
}
__device__ __forceinline__ void cp_async16(uint32_t s, const void* g) {
    asm volatile("cp.async.cg.shared.global [%0], [%1], 16;" :: "r"(s), "l"(g));
}
#define CP_COMMIT()  asm volatile("cp.async.commit_group;" ::: "memory")
#define CP_WAIT(n)   asm volatile("cp.async.wait_group %0;" :: "n"(n) : "memory")

__device__ __forceinline__ void ldsm4(uint32_t* r, uint32_t addr) {
    asm volatile("ldmatrix.sync.aligned.m8n8.x4.shared.b16 {%0,%1,%2,%3}, [%4];"
                 : "=r"(r[0]), "=r"(r[1]), "=r"(r[2]), "=r"(r[3]) : "r"(addr));
}
__device__ __forceinline__ void mma_bf16(float* d, const uint32_t* a, uint32_t b0, uint32_t b1) {
    asm volatile(
        "mma.sync.aligned.m16n8k16.row.col.f32.bf16.bf16.f32 "
        "{%0,%1,%2,%3}, {%4,%5,%6,%7}, {%8,%9}, {%0,%1,%2,%3};"
        : "+f"(d[0]), "+f"(d[1]), "+f"(d[2]), "+f"(d[3])
        : "r"(a[0]), "r"(a[1]), "r"(a[2]), "r"(a[3]), "r"(b0), "r"(b1));
}

// ---------------------------------------------------------------------------
// Split fp32 -> (hi, lo) bf16 planes. lo = bf16(x - float(hi)).
// ---------------------------------------------------------------------------
__global__ __launch_bounds__(256)
void split_kernel(const float* __restrict__ src, __nv_bfloat16* __restrict__ hi,
                  __nv_bfloat16* __restrict__ lo, int n4)
{
    int i = blockIdx.x * blockDim.x + threadIdx.x;
    if (i >= n4) return;
    float4 x = ((const float4*)src)[i];
    __nv_bfloat16 h0 = __float2bfloat16(x.x);
    __nv_bfloat16 h1 = __float2bfloat16(x.y);
    __nv_bfloat16 h2 = __float2bfloat16(x.z);
    __nv_bfloat16 h3 = __float2bfloat16(x.w);
    __nv_bfloat162 H0; H0.x = h0; H0.y = h1;
    __nv_bfloat162 H1; H1.x = h2; H1.y = h3;
    ((__nv_bfloat162*)hi)[i*2]   = H0;
    ((__nv_bfloat162*)hi)[i*2+1] = H1;
    __nv_bfloat162 L0, L1;
    L0.x = __float2bfloat16(x.x - __bfloat162float(h0));
    L0.y = __float2bfloat16(x.y - __bfloat162float(h1));
    L1.x = __float2bfloat16(x.z - __bfloat162float(h2));
    L1.y = __float2bfloat16(x.w - __bfloat162float(h3));
    ((__nv_bfloat162*)lo)[i*2]   = L0;
    ((__nv_bfloat162*)lo)[i*2+1] = L1;
}

// ---------------------------------------------------------------------------
// bf16-split GEMM via mma.sync:
//   C[M,N] = (Ahi+Alo)[M,K] * (Bhi+Blo)[N,K]^T (+bias)
// CTA tile 128x128, BK=32, 8 warps (32x64 each), 3-stage cp.async pipeline.
// SMEM rows padded to 80B (40 bf16) -> conflict-free ldmatrix.
// ---------------------------------------------------------------------------
#define GBK       32
#define ROW_B     80                   // padded row bytes (32 bf16 data + 8 pad)
#define PLANE_B   (128 * ROW_B)        // 10240
#define STAGE_B   (4 * PLANE_B)        // 40960  (Ahi,Alo,Bhi,Blo)
#define NSTAGE    3
#define GSMEM     (NSTAGE * STAGE_B)   // 122880

__device__ __forceinline__ void load_stage(uint32_t st_u32,
    const __nv_bfloat16* __restrict__ Ahi, const __nv_bfloat16* __restrict__ Alo,
    const __nv_bfloat16* __restrict__ Bhi, const __nv_bfloat16* __restrict__ Blo,
    int m0, int n0, int K, int kc, int tid)
{
#pragma unroll
    for (int p = 0; p < 4; p++) {
        const __nv_bfloat16* src = (p == 0) ? Ahi : (p == 1) ? Alo : (p == 2) ? Bhi : Blo;
        const int rbase = (p < 2) ? m0 : n0;
#pragma unroll
        for (int i = 0; i < 2; i++) {
            int idx = i * 256 + tid;
            int r = idx >> 2, c = idx & 3;
            const void* g = src + (size_t)(rbase + r) * K + kc + c * 8;
            cp_async16(st_u32 + p * PLANE_B + r * ROW_B + c * 16, g);
        }
    }
}

__global__ __launch_bounds__(256, 1)
void gemm_mma_kernel(const __nv_bfloat16* __restrict__ Ahi, const __nv_bfloat16* __restrict__ Alo,
                     const __nv_bfloat16* __restrict__ Bhi, const __nv_bfloat16* __restrict__ Blo,
                     const float* __restrict__ bias, float* __restrict__ C,
                     int M, int N, int K)
{
    extern __shared__ char smem[];
    const uint32_t sm0 = smem_u32(smem);
    const int tid  = threadIdx.x;
    const int wid  = tid >> 5;
    const int lane = tid & 31;
    const int wm   = wid & 3;          // warp row  (32 rows each)
    const int wn   = wid >> 2;         // warp col  (64 cols each)
    const int m0 = blockIdx.y * 128;
    const int n0 = blockIdx.x * 128;
    const int nchunk = K / GBK;

    float acc[2][8][4];
#pragma unroll
    for (int mt = 0; mt < 2; mt++)
#pragma unroll
        for (int nt = 0; nt < 8; nt++)
#pragma unroll
            for (int q = 0; q < 4; q++) acc[mt][nt][q] = 0.f;

    // ldmatrix lane addressing: row = tilebase + (lane&15), khalf = lane>>4
    const int lrow  = lane & 15;
    const int lkoff = (lane >> 4) * 16;   // bytes

    // Prologue: stages 0 and 1
    load_stage(sm0,           Ahi, Alo, Bhi, Blo, m0, n0, K, 0,   tid);
    CP_COMMIT();
    load_stage(sm0 + STAGE_B, Ahi, Alo, Bhi, Blo, m0, n0, K, GBK, tid);
    CP_COMMIT();

    for (int i = 0; i < nchunk; i++) {
        CP_WAIT(1);
        __syncthreads();

        if (i + 2 < nchunk)
            load_stage(sm0 + ((i + 2) % NSTAGE) * STAGE_B,
                       Ahi, Alo, Bhi, Blo, m0, n0, K, (i + 2) * GBK, tid);
        CP_COMMIT();

        const uint32_t st = sm0 + (i % NSTAGE) * STAGE_B;
        const uint32_t aRow = st + (wm * 32 + lrow) * ROW_B + lkoff;              // + plane, +mt*16*ROW_B, +kstep*32
        const uint32_t bRow = st + 2 * PLANE_B + (wn * 64 + lrow) * ROW_B + lkoff;

#pragma unroll
        for (int ks = 0; ks < 2; ks++) {
            uint32_t ah[2][4], al[2][4], bh[4][4], bl[4][4];
#pragma unroll
            for (int mt = 0; mt < 2; mt++) {
                ldsm4(ah[mt], aRow             + mt * (16 * ROW_B) + ks * 32);
                ldsm4(al[mt], aRow + PLANE_B   + mt * (16 * ROW_B) + ks * 32);
            }
#pragma unroll
            for (int np = 0; np < 4; np++) {
                ldsm4(bh[np], bRow             + np * (16 * ROW_B) + ks * 32);
                ldsm4(bl[np], bRow + PLANE_B   + np * (16 * ROW_B) + ks * 32);
            }
#pragma unroll
            for (int mt = 0; mt < 2; mt++)
#pragma unroll
                for (int nt = 0; nt < 8; nt++) {
                    const int np = nt >> 1, h = nt & 1;
                    mma_bf16(acc[mt][nt], ah[mt], bh[np][h], bh[np][2 + h]);
                    mma_bf16(acc[mt][nt], al[mt], bh[np][h], bh[np][2 + h]);
                    mma_bf16(acc[mt][nt], ah[mt], bl[np][h], bl[np][2 + h]);
                }
        }
        __syncthreads();
    }

    // Epilogue: C fragment layout of m16n8k16
    const int grp = lane >> 2;        // row within 8
    const int tig = lane & 3;         // col pair index
#pragma unroll
    for (int mt = 0; mt < 2; mt++) {
        const int rbase = m0 + wm * 32 + mt * 16 + grp;
#pragma unroll
        for (int nt = 0; nt < 8; nt++) {
            const int col = n0 + wn * 64 + nt * 8 + tig * 2;
            float bx = 0.f, by = 0.f;
            if (bias) { bx = bias[col]; by = bias[col + 1]; }
            float2 v0; v0.x = acc[mt][nt][0] + bx; v0.y = acc[mt][nt][1] + by;
            float2 v1; v1.x = acc[mt][nt][2] + bx; v1.y = acc[mt][nt][3] + by;
            *(float2*)(C + (size_t)rbase * N + col)       = v0;
            *(float2*)(C + (size_t)(rbase + 8) * N + col) = v1;
        }
    }
}

// ---------------------------------------------------------------------------
// RoPE (in place)
// ---------------------------------------------------------------------------
__global__ __launch_bounds__(256)
void rope_kernel(float* __restrict__ T)
{
    int idx = blockIdx.x * blockDim.x + threadIdx.x;
    int i = idx & 63;
    int h = (idx >> 6) & (NHEAD - 1);
    int s = (idx >> 10) & (SEQ - 1);
    int b = idx >> 21;

    float inv = expf(-9.210340371976184f * ((float)i * (1.0f / 64.0f)));
    float ang = (float)s * inv;
    float c, sn;
    sincosf(ang, &sn, &c);

    float* base = T + (size_t)(b * SEQ + s) * DIM + h * HD;
    float t1 = base[i];
    float t2 = base[i + 64];
    base[i]      = t1 * c - t2 * sn;
    base[i + 64] = t2 * c + t1 * sn;
}

// ---------------------------------------------------------------------------
// Causal flash attention, fp32 (unchanged)
// ---------------------------------------------------------------------------
#define AM 64
#define AN 64
#define PS_STRIDE 65
#define ATTN_SMEM_FLOATS (128*64 + 128*64 + 64*128 + 64*PS_STRIDE + 192)
#define ATTN_SMEM_BYTES  (ATTN_SMEM_FLOATS * 4)

__global__ __launch_bounds__(256, 1)
void attn_kernel(const float* __restrict__ Q, const float* __restrict__ K,
                 const float* __restrict__ V, float* __restrict__ O)
{
    extern __shared__ float sm[];
    float* Qs    = sm;
    float* Ks    = Qs + 128 * 64;
    float* Vs    = Ks + 128 * 64;
    float* Ps    = Vs + 64 * 128;
    float* row_m = Ps + 64 * PS_STRIDE;
    float* row_l = row_m + 64;
    float* row_a = row_l + 64;

    const int tid = threadIdx.x;
    const int bh  = blockIdx.y;
    const int b   = bh >> 4;
    const int h   = bh & (NHEAD - 1);
    const int qt  = blockIdx.x;
    const int q0  = qt * AM;

    const float* Qb = Q + (size_t)(b * SEQ + q0) * DIM + h * HD;

#pragma unroll
    for (int u = 0; u < 8; u++) {
        int li = u * 256 + tid;
        int r  = li & 63;
        int d4 = li >> 6;
        float4 t = *(const float4*)&Qb[(size_t)r * DIM + d4 * 4];
        int dd = d4 * 4;
        Qs[(dd+0)*64 + r] = t.x;
        Qs[(dd+1)*64 + r] = t.y;
        Qs[(dd+2)*64 + r] = t.z;
        Qs[(dd+3)*64 + r] = t.w;
    }
    if (tid < 64) { row_m[tid] = -1e30f; row_l[tid] = 0.f; }

    float Ot[4][8];
#pragma unroll
    for (int i = 0; i < 4; i++)
#pragma unroll
        for (int c = 0; c < 8; c++) Ot[i][c] = 0.f;

    const int ty  = tid >> 4;
    const int tx  = tid & 15;
    const int tm  = ty * 4;
    const int tn  = tx * 4;
    const int col = tx * 8;
    const float scale = 0.08838834764831845f;

    __syncthreads();

    for (int kt = 0; kt <= qt; kt++) {
        const int k0 = kt * AN;
        const float* Kb = K + (size_t)(b * SEQ + k0) * DIM + h * HD;
        const float* Vb = V + (size_t)(b * SEQ + k0) * DIM + h * HD;

#pragma unroll
        for (int u = 0; u < 8; u++) {
            int li = u * 256 + tid;
            {
                int r = li & 63, d4 = li >> 6;
                float4 t = *(const float4*)&Kb[(size_t)r * DIM + d4 * 4];
                int dd = d4 * 4;
                Ks[(dd+0)*64 + r] = t.x;
                Ks[(dd+1)*64 + r] = t.y;
                Ks[(dd+2)*64 + r] = t.z;
                Ks[(dd+3)*64 + r] = t.w;
            }
            {
                int d4 = li & 31, r = li >> 5;
                *(float4*)&Vs[r * 128 + d4 * 4] =
                    *(const float4*)&Vb[(size_t)r * DIM + d4 * 4];
            }
        }
        __syncthreads();

        float s4[4][4];
#pragma unroll
        for (int i = 0; i < 4; i++)
#pragma unroll
            for (int j = 0; j < 4; j++) s4[i][j] = 0.f;

#pragma unroll 4
        for (int d = 0; d < 128; d++) {
            float4 a  = *(const float4*)&Qs[d * 64 + tm];
            float4 bb = *(const float4*)&Ks[d * 64 + tn];
            s4[0][0] += a.x*bb.x; s4[0][1] += a.x*bb.y; s4[0][2] += a.x*bb.z; s4[0][3] += a.x*bb.w;
            s4[1][0] += a.y*bb.x; s4[1][1] += a.y*bb.y; s4[1][2] += a.y*bb.z; s4[1][3] += a.y*bb.w;
            s4[2][0] += a.z*bb.x; s4[2][1] += a.z*bb.y; s4[2][2] += a.z*bb.z; s4[2][3] += a.z*bb.w;
            s4[3][0] += a.w*bb.x; s4[3][1] += a.w*bb.y; s4[3][2] += a.w*bb.z; s4[3][3] += a.w*bb.w;
        }

        const bool diag = (kt == qt);
#pragma unroll
        for (int i = 0; i < 4; i++)
#pragma unroll
            for (int j = 0; j < 4; j++) {
                float v = s4[i][j] * scale;
                if (diag && (k0 + tn + j > q0 + tm + i)) v = -1e9f;
                Ps[(tm + i) * PS_STRIDE + tn + j] = v;
            }
        __syncthreads();

        if (tid < 64) {
            int r = tid;
            float mold = row_m[r];
            float mx = mold;
#pragma unroll 8
            for (int j = 0; j < 64; j++) mx = fmaxf(mx, Ps[r * PS_STRIDE + j]);
            float alpha = expf(mold - mx);
            float l = row_l[r] * alpha;
#pragma unroll 8
            for (int j = 0; j < 64; j++) {
                float p = expf(Ps[r * PS_STRIDE + j] - mx);
                Ps[r * PS_STRIDE + j] = p;
                l += p;
            }
            row_m[r] = mx; row_l[r] = l; row_a[r] = alpha;
        }
        __syncthreads();

        float al[4];
#pragma unroll
        for (int i = 0; i < 4; i++) al[i] = row_a[tm + i];
#pragma unroll
        for (int i = 0; i < 4; i++)
#pragma unroll
            for (int c = 0; c < 8; c++) Ot[i][c] *= al[i];

#pragma unroll 2
        for (int j = 0; j < 64; j++) {
            float4 v0 = *(const float4*)&Vs[j * 128 + col];
            float4 v1 = *(const float4*)&Vs[j * 128 + col + 4];
#pragma unroll
            for (int i = 0; i < 4; i++) {
                float p = Ps[(tm + i) * PS_STRIDE + j];
                Ot[i][0] += p * v0.x; Ot[i][1] += p * v0.y;
                Ot[i][2] += p * v0.z; Ot[i][3] += p * v0.w;
                Ot[i][4] += p * v1.x; Ot[i][5] += p * v1.y;
                Ot[i][6] += p * v1.z; Ot[i][7] += p * v1.w;
            }
        }
        __syncthreads();
    }

    float* Ob = O + (size_t)(b * SEQ + q0) * DIM + h * HD;
#pragma unroll
    for (int i = 0; i < 4; i++) {
        float invl = 1.f / row_l[tm + i];
        float4 o0, o1;
        o0.x = Ot[i][0]*invl; o0.y = Ot[i][1]*invl; o0.z = Ot[i][2]*invl; o0.w = Ot[i][3]*invl;
        o1.x = Ot[i][4]*invl; o1.y = Ot[i][5]*invl; o1.z = Ot[i][6]*invl; o1.w = Ot[i][7]*invl;
        *(float4*)&Ob[(size_t)(tm + i) * DIM + col]     = o0;
        *(float4*)&Ob[(size_t)(tm + i) * DIM + col + 4] = o1;
    }
}

// ---------------------------------------------------------------------------
extern "C" void kernel_launch(void* const* d_in, const int* in_sizes, int n_in,
                              void* d_out, int out_size)
{
    (void)in_sizes; (void)n_in; (void)out_size;
    const float* x  = (const float*)d_in[0];
    const float* Wq = (const float*)d_in[1];
    const float* Wk = (const float*)d_in[2];
    const float* Wv = (const float*)d_in[3];
    const float* Wo = (const float*)d_in[4];
    const float* bo = (const float*)d_in[5];
    float* out = (float*)d_out;

    float *q, *k, *v, *att;
    __nv_bfloat16 *xhi, *xlo, *ahi, *alo, *whi, *wlo;
    cudaGetSymbolAddress((void**)&q,   g_q);
    cudaGetSymbolAddress((void**)&k,   g_k);
    cudaGetSymbolAddress((void**)&v,   g_v);
    cudaGetSymbolAddress((void**)&att, g_att);
    cudaGetSymbolAddress((void**)&xhi, g_xhi);
    cudaGetSymbolAddress((void**)&xlo, g_xlo);
    cudaGetSymbolAddress((void**)&ahi, g_ahi);
    cudaGetSymbolAddress((void**)&alo, g_alo);
    cudaGetSymbolAddress((void**)&whi, g_whi);
    cudaGetSymbolAddress((void**)&wlo, g_wlo);

    const size_t WSZ = (size_t)DIM * DIM;
    const int nx4 = (MROWS * DIM) / 4;
    const int nw4 = (DIM * DIM) / 4;

    split_kernel<<<nx4 / 256, 256>>>(x, xhi, xlo, nx4);
    split_kernel<<<nw4 / 256, 256>>>(Wq, whi + 0 * WSZ, wlo + 0 * WSZ, nw4);
    split_kernel<<<nw4 / 256, 256>>>(Wk, whi + 1 * WSZ, wlo + 1 * WSZ, nw4);
    split_kernel<<<nw4 / 256, 256>>>(Wv, whi + 2 * WSZ, wlo + 2 * WSZ, nw4);
    split_kernel<<<nw4 / 256, 256>>>(Wo, whi + 3 * WSZ, wlo + 3 * WSZ, nw4);

    cudaFuncSetAttribute(gemm_mma_kernel,
                         cudaFuncAttributeMaxDynamicSharedMemorySize, GSMEM);

    dim3 ggrid(DIM / 128, MROWS / 128);   // (16, 64)
    gemm_mma_kernel<<<ggrid, 256, GSMEM>>>(xhi, xlo, whi + 0 * WSZ, wlo + 0 * WSZ,
                                           nullptr, q, MROWS, DIM, DIM);
    gemm_mma_kernel<<<ggrid, 256, GSMEM>>>(xhi, xlo, whi + 1 * WSZ, wlo + 1 * WSZ,
                                           nullptr, k, MROWS, DIM, DIM);
    gemm_mma_kernel<<<ggrid, 256, GSMEM>>>(xhi, xlo, whi + 2 * WSZ, wlo + 2 * WSZ,
                                           nullptr, v, MROWS, DIM, DIM);

    int rope_threads = BATCH * SEQ * NHEAD * 64;
    rope_kernel<<<rope_threads / 256, 256>>>(q);
    rope_kernel<<<rope_threads / 256, 256>>>(k);

    cudaFuncSetAttribute(attn_kernel,
                         cudaFuncAttributeMaxDynamicSharedMemorySize,
                         ATTN_SMEM_BYTES);
    attn_kernel<<<dim3(SEQ / AM, BATCH * NHEAD), 256, ATTN_SMEM_BYTES>>>(q, k, v, att);

    split_kernel<<<nx4 / 256, 256>>>(att, ahi, alo, nx4);
    gemm_mma_kernel<<<ggrid, 256, GSMEM>>>(ahi, alo, whi + 3 * WSZ, wlo + 3 * WSZ,
                                           bo, out, MROWS, DIM, DIM);
}

// round 5
// speedup vs baseline: 2.4652x; 1.5422x over previous
#include <cuda_runtime.h>
#include <cuda_bf16.h>
#include <math.h>
#include <stdint.h>

#define BATCH 4
#define SEQ   2048
#define DIM   2048
#define NHEAD 16
#define HD    128
#define MROWS (BATCH*SEQ)   // 8192

// ---------------- scratch (static device globals) ----------------
__device__ float g_q[(size_t)MROWS * DIM];
__device__ float g_k[(size_t)MROWS * DIM];
__device__ float g_v[(size_t)MROWS * DIM];
__device__ __nv_bfloat16 g_xhi[(size_t)MROWS * DIM];
__device__ __nv_bfloat16 g_xlo[(size_t)MROWS * DIM];
__device__ __nv_bfloat16 g_ahi[(size_t)MROWS * DIM];
__device__ __nv_bfloat16 g_alo[(size_t)MROWS * DIM];
__device__ __nv_bfloat16 g_qhi[(size_t)MROWS * DIM];
__device__ __nv_bfloat16 g_qlo[(size_t)MROWS * DIM];
__device__ __nv_bfloat16 g_khi[(size_t)MROWS * DIM];
__device__ __nv_bfloat16 g_klo[(size_t)MROWS * DIM];
__device__ __nv_bfloat16 g_vhi[(size_t)MROWS * DIM];
__device__ __nv_bfloat16 g_vlo[(size_t)MROWS * DIM];
__device__ __nv_bfloat16 g_whi[4][(size_t)DIM * DIM];
__device__ __nv_bfloat16 g_wlo[4][(size_t)DIM * DIM];

// ---------------- low-level helpers ----------------
__device__ __forceinline__ uint32_t smem_u32(const void* p) {
    uint32_t a;
    asm("{ .reg .u64 t; cvta.to.shared.u64 t, %1; cvt.u32.u64 %0, t; }" : "=r"(a) : "l"(p));
    return a;
}
__device__ __forceinline__ void cp_async16(uint32_t s, const void* g) {
    asm volatile("cp.async.cg.shared.global [%0], [%1], 16;" :: "r"(s), "l"(g));
}
#define CP_COMMIT()  asm volatile("cp.async.commit_group;" ::: "memory")
#define CP_WAIT(n)   asm volatile("cp.async.wait_group %0;" :: "n"(n) : "memory")

__device__ __forceinline__ void ldsm4(uint32_t* r, uint32_t addr) {
    asm volatile("ldmatrix.sync.aligned.m8n8.x4.shared.b16 {%0,%1,%2,%3}, [%4];"
                 : "=r"(r[0]), "=r"(r[1]), "=r"(r[2]), "=r"(r[3]) : "r"(addr));
}
__device__ __forceinline__ void mma_bf16(float* d, const uint32_t* a, uint32_t b0, uint32_t b1) {
    asm volatile(
        "mma.sync.aligned.m16n8k16.row.col.f32.bf16.bf16.f32 "
        "{%0,%1,%2,%3}, {%4,%5,%6,%7}, {%8,%9}, {%0,%1,%2,%3};"
        : "+f"(d[0]), "+f"(d[1]), "+f"(d[2]), "+f"(d[3])
        : "r"(a[0]), "r"(a[1]), "r"(a[2]), "r"(a[3]), "r"(b0), "r"(b1));
}

// ---------------------------------------------------------------------------
// Split fp32 -> (hi, lo) bf16 planes. lo = bf16(x - float(hi)).
// ---------------------------------------------------------------------------
__global__ __launch_bounds__(256)
void split_kernel(const float* __restrict__ src, __nv_bfloat16* __restrict__ hi,
                  __nv_bfloat16* __restrict__ lo, int n4)
{
    int i = blockIdx.x * blockDim.x + threadIdx.x;
    if (i >= n4) return;
    float4 x = ((const float4*)src)[i];
    __nv_bfloat16 h0 = __float2bfloat16(x.x);
    __nv_bfloat16 h1 = __float2bfloat16(x.y);
    __nv_bfloat16 h2 = __float2bfloat16(x.z);
    __nv_bfloat16 h3 = __float2bfloat16(x.w);
    __nv_bfloat162 H0; H0.x = h0; H0.y = h1;
    __nv_bfloat162 H1; H1.x = h2; H1.y = h3;
    ((__nv_bfloat162*)hi)[i*2]   = H0;
    ((__nv_bfloat162*)hi)[i*2+1] = H1;
    __nv_bfloat162 L0, L1;
    L0.x = __float2bfloat16(x.x - __bfloat162float(h0));
    L0.y = __float2bfloat16(x.y - __bfloat162float(h1));
    L1.x = __float2bfloat16(x.z - __bfloat162float(h2));
    L1.y = __float2bfloat16(x.w - __bfloat162float(h3));
    ((__nv_bfloat162*)lo)[i*2]   = L0;
    ((__nv_bfloat162*)lo)[i*2+1] = L1;
}

// ---------------------------------------------------------------------------
// Fused RoPE + bf16 split: reads fp32, rotates, writes hi/lo bf16 planes.
// ---------------------------------------------------------------------------
__global__ __launch_bounds__(256)
void rope_split_kernel(const float* __restrict__ src,
                       __nv_bfloat16* __restrict__ hi, __nv_bfloat16* __restrict__ lo)
{
    int idx = blockIdx.x * blockDim.x + threadIdx.x;
    int i = idx & 63;
    int h = (idx >> 6) & (NHEAD - 1);
    int s = (idx >> 10) & (SEQ - 1);
    int b = idx >> 21;

    float inv = expf(-9.210340371976184f * ((float)i * (1.0f / 64.0f)));
    float ang = (float)s * inv;
    float c, sn;
    sincosf(ang, &sn, &c);

    size_t base = (size_t)(b * SEQ + s) * DIM + h * HD;
    float t1 = src[base + i];
    float t2 = src[base + i + 64];
    float o1 = t1 * c - t2 * sn;
    float o2 = t2 * c + t1 * sn;

    __nv_bfloat16 h1 = __float2bfloat16(o1);
    __nv_bfloat16 h2 = __float2bfloat16(o2);
    hi[base + i]      = h1;
    hi[base + i + 64] = h2;
    lo[base + i]      = __float2bfloat16(o1 - __bfloat162float(h1));
    lo[base + i + 64] = __float2bfloat16(o2 - __bfloat162float(h2));
}

// ---------------------------------------------------------------------------
// bf16-split GEMM via mma.sync (verified in R3)
// ---------------------------------------------------------------------------
#define GBK       32
#define ROW_B     80
#define PLANE_B   (128 * ROW_B)
#define STAGE_B   (4 * PLANE_B)
#define NSTAGE    3
#define GSMEM     (NSTAGE * STAGE_B)

__device__ __forceinline__ void load_stage(uint32_t st_u32,
    const __nv_bfloat16* __restrict__ Ahi, const __nv_bfloat16* __restrict__ Alo,
    const __nv_bfloat16* __restrict__ Bhi, const __nv_bfloat16* __restrict__ Blo,
    int m0, int n0, int K, int kc, int tid)
{
#pragma unroll
    for (int p = 0; p < 4; p++) {
        const __nv_bfloat16* src = (p == 0) ? Ahi : (p == 1) ? Alo : (p == 2) ? Bhi : Blo;
        const int rbase = (p < 2) ? m0 : n0;
#pragma unroll
        for (int i = 0; i < 2; i++) {
            int idx = i * 256 + tid;
            int r = idx >> 2, c = idx & 3;
            const void* g = src + (size_t)(rbase + r) * K + kc + c * 8;
            cp_async16(st_u32 + p * PLANE_B + r * ROW_B + c * 16, g);
        }
    }
}

__global__ __launch_bounds__(256, 1)
void gemm_mma_kernel(const __nv_bfloat16* __restrict__ Ahi, const __nv_bfloat16* __restrict__ Alo,
                     const __nv_bfloat16* __restrict__ Bhi, const __nv_bfloat16* __restrict__ Blo,
                     const float* __restrict__ bias, float* __restrict__ C,
                     int M, int N, int K)
{
    extern __shared__ char smem[];
    const uint32_t sm0 = smem_u32(smem);
    const int tid  = threadIdx.x;
    const int wid  = tid >> 5;
    const int lane = tid & 31;
    const int wm   = wid & 3;
    const int wn   = wid >> 2;
    const int m0 = blockIdx.y * 128;
    const int n0 = blockIdx.x * 128;
    const int nchunk = K / GBK;

    float acc[2][8][4];
#pragma unroll
    for (int mt = 0; mt < 2; mt++)
#pragma unroll
        for (int nt = 0; nt < 8; nt++)
#pragma unroll
            for (int q = 0; q < 4; q++) acc[mt][nt][q] = 0.f;

    const int lrow  = lane & 15;
    const int lkoff = (lane >> 4) * 16;

    load_stage(sm0,           Ahi, Alo, Bhi, Blo, m0, n0, K, 0,   tid);
    CP_COMMIT();
    load_stage(sm0 + STAGE_B, Ahi, Alo, Bhi, Blo, m0, n0, K, GBK, tid);
    CP_COMMIT();

    for (int i = 0; i < nchunk; i++) {
        CP_WAIT(1);
        __syncthreads();

        if (i + 2 < nchunk)
            load_stage(sm0 + ((i + 2) % NSTAGE) * STAGE_B,
                       Ahi, Alo, Bhi, Blo, m0, n0, K, (i + 2) * GBK, tid);
        CP_COMMIT();

        const uint32_t st = sm0 + (i % NSTAGE) * STAGE_B;
        const uint32_t aRow = st + (wm * 32 + lrow) * ROW_B + lkoff;
        const uint32_t bRow = st + 2 * PLANE_B + (wn * 64 + lrow) * ROW_B + lkoff;

#pragma unroll
        for (int ks = 0; ks < 2; ks++) {
            uint32_t ah[2][4], al[2][4], bh[4][4], bl[4][4];
#pragma unroll
            for (int mt = 0; mt < 2; mt++) {
                ldsm4(ah[mt], aRow             + mt * (16 * ROW_B) + ks * 32);
                ldsm4(al[mt], aRow + PLANE_B   + mt * (16 * ROW_B) + ks * 32);
            }
#pragma unroll
            for (int np = 0; np < 4; np++) {
                ldsm4(bh[np], bRow             + np * (16 * ROW_B) + ks * 32);
                ldsm4(bl[np], bRow + PLANE_B   + np * (16 * ROW_B) + ks * 32);
            }
#pragma unroll
            for (int mt = 0; mt < 2; mt++)
#pragma unroll
                for (int nt = 0; nt < 8; nt++) {
                    const int np = nt >> 1, h = nt & 1;
                    mma_bf16(acc[mt][nt], ah[mt], bh[np][h], bh[np][2 + h]);
                    mma_bf16(acc[mt][nt], al[mt], bh[np][h], bh[np][2 + h]);
                    mma_bf16(acc[mt][nt], ah[mt], bl[np][h], bl[np][2 + h]);
                }
        }
        __syncthreads();
    }

    const int grp = lane >> 2;
    const int tig = lane & 3;
#pragma unroll
    for (int mt = 0; mt < 2; mt++) {
        const int rbase = m0 + wm * 32 + mt * 16 + grp;
#pragma unroll
        for (int nt = 0; nt < 8; nt++) {
            const int col = n0 + wn * 64 + nt * 8 + tig * 2;
            float bx = 0.f, by = 0.f;
            if (bias) { bx = bias[col]; by = bias[col + 1]; }
            float2 v0; v0.x = acc[mt][nt][0] + bx; v0.y = acc[mt][nt][1] + by;
            float2 v1; v1.x = acc[mt][nt][2] + bx; v1.y = acc[mt][nt][3] + by;
            *(float2*)(C + (size_t)rbase * N + col)       = v0;
            *(float2*)(C + (size_t)(rbase + 8) * N + col) = v1;
        }
    }
}

// ---------------------------------------------------------------------------
// Causal flash attention via mma.sync bf16-split.
// CTA: 128 q-rows x 64 k per iter, 8 warps (16 q-rows each).
// Writes ahi/alo bf16 planes directly.
// ---------------------------------------------------------------------------
#define SKB 272            // Q/K smem row bytes (128 bf16 = 256B + 16 pad)
#define SVB 144            // Vt smem row bytes (64 bf16 = 128B + 16 pad)
#define AQHI 0
#define AQLO (AQHI + 128*SKB)
#define AKHI (AQLO + 128*SKB)
#define AKLO (AKHI + 64*SKB)
#define AVHI (AKLO + 64*SKB)
#define AVLO (AVHI + 128*SVB)
#define ASMEM (AVLO + 128*SVB)   // 141312

__global__ __launch_bounds__(256, 1)
void attn_mma_kernel(const __nv_bfloat16* __restrict__ Qhi, const __nv_bfloat16* __restrict__ Qlo,
                     const __nv_bfloat16* __restrict__ Khi, const __nv_bfloat16* __restrict__ Klo,
                     const __nv_bfloat16* __restrict__ Vhi, const __nv_bfloat16* __restrict__ Vlo,
                     __nv_bfloat16* __restrict__ Ohi, __nv_bfloat16* __restrict__ Olo)
{
    extern __shared__ char smem[];
    const uint32_t s0 = smem_u32(smem);
    const int tid  = threadIdx.x;
    const int w    = tid >> 5;
    const int lane = tid & 31;
    const int grp  = lane >> 2;
    const int tig  = lane & 3;
    const int lrow  = lane & 15;
    const int lkoff = (lane >> 4) * 16;

    const int bh = blockIdx.y;
    const int b  = bh >> 4;
    const int h  = bh & (NHEAD - 1);
    const int qt = blockIdx.x;
    const int q0 = qt * 128;

    const size_t rowQ = (size_t)(b * SEQ + q0);
    const __nv_bfloat16* qh_g = Qhi + rowQ * DIM + h * HD;
    const __nv_bfloat16* ql_g = Qlo + rowQ * DIM + h * HD;

    // Q tile -> smem (both planes)
#pragma unroll
    for (int u = 0; u < 8; u++) {
        int idx = u * 256 + tid;
        int r = idx >> 4, c = idx & 15;
        cp_async16(s0 + AQHI + r * SKB + c * 16, qh_g + (size_t)r * DIM + c * 8);
        cp_async16(s0 + AQLO + r * SKB + c * 16, ql_g + (size_t)r * DIM + c * 8);
    }
    CP_COMMIT();

    float m[2] = {-1e30f, -1e30f};
    float l[2] = {0.f, 0.f};
    float Oa[16][4];
#pragma unroll
    for (int nt = 0; nt < 16; nt++)
#pragma unroll
        for (int q = 0; q < 4; q++) Oa[nt][q] = 0.f;

    const float scale = 0.08838834764831845f;   // 1/sqrt(128)
    const int nkt = 2 * qt + 2;

    for (int kt = 0; kt < nkt; kt++) {
        const int kv0 = kt * 64;
        const size_t rowK = (size_t)(b * SEQ + kv0);
        const __nv_bfloat16* kh_g = Khi + rowK * DIM + h * HD;
        const __nv_bfloat16* kl_g = Klo + rowK * DIM + h * HD;
        const __nv_bfloat16* vh_g = Vhi + rowK * DIM + h * HD;
        const __nv_bfloat16* vl_g = Vlo + rowK * DIM + h * HD;

        __syncthreads();   // previous tile's consumers done with K/V smem

        // K tile (both planes) via cp.async
#pragma unroll
        for (int u = 0; u < 4; u++) {
            int idx = u * 256 + tid;
            int r = idx >> 4, c = idx & 15;
            cp_async16(s0 + AKHI + r * SKB + c * 16, kh_g + (size_t)r * DIM + c * 8);
            cp_async16(s0 + AKLO + r * SKB + c * 16, kl_g + (size_t)r * DIM + c * 8);
        }
        CP_COMMIT();

        // V tile transposed into smem: Vt[d][kv]
#pragma unroll
        for (int u = 0; u < 4; u++) {
            int idx = u * 256 + tid;
            int kv = idx & 63, c = idx >> 6;   // c: 0..15, d0 = 8c
            uint4 xh = *(const uint4*)(vh_g + (size_t)kv * DIM + c * 8);
            uint4 xl = *(const uint4*)(vl_g + (size_t)kv * DIM + c * 8);
            const uint16_t* uh = (const uint16_t*)&xh;
            const uint16_t* ul = (const uint16_t*)&xl;
#pragma unroll
            for (int j = 0; j < 8; j++) {
                *(uint16_t*)(smem + AVHI + (c * 8 + j) * SVB + kv * 2) = uh[j];
                *(uint16_t*)(smem + AVLO + (c * 8 + j) * SVB + kv * 2) = ul[j];
            }
        }
        CP_WAIT(0);
        __syncthreads();

        // ---- S = Q K^T (3-pass split) ----
        float Sa[8][4];
#pragma unroll
        for (int j = 0; j < 8; j++)
#pragma unroll
            for (int q = 0; q < 4; q++) Sa[j][q] = 0.f;

        const uint32_t aBase = s0 + (w * 16 + lrow) * SKB + lkoff;
        const uint32_t kBase = s0 + lrow * SKB + lkoff;
#pragma unroll
        for (int ks = 0; ks < 8; ks++) {
            uint32_t ah[4], al[4];
            ldsm4(ah, aBase + AQHI + ks * 32);
            ldsm4(al, aBase + AQLO + ks * 32);
#pragma unroll
            for (int p = 0; p < 4; p++) {
                uint32_t kb[4];
                ldsm4(kb, kBase + AKHI + p * 16 * SKB + ks * 32);
                mma_bf16(Sa[2*p],   ah, kb[0], kb[2]);
                mma_bf16(Sa[2*p+1], ah, kb[1], kb[3]);
                mma_bf16(Sa[2*p],   al, kb[0], kb[2]);
                mma_bf16(Sa[2*p+1], al, kb[1], kb[3]);
                ldsm4(kb, kBase + AKLO + p * 16 * SKB + ks * 32);
                mma_bf16(Sa[2*p],   ah, kb[0], kb[2]);
                mma_bf16(Sa[2*p+1], ah, kb[1], kb[3]);
            }
        }

        // ---- scale + causal mask ----
        const int r0g = q0 + w * 16 + grp;
        const int r1g = r0g + 8;
        const bool need_mask = (kt >= 2 * qt);
#pragma unroll
        for (int j = 0; j < 8; j++) {
            const int c0 = kv0 + j * 8 + tig * 2;
            Sa[j][0] *= scale; Sa[j][1] *= scale;
            Sa[j][2] *= scale; Sa[j][3] *= scale;
            if (need_mask) {
                if (c0     > r0g) Sa[j][0] = -1e9f;
                if (c0 + 1 > r0g) Sa[j][1] = -1e9f;
                if (c0     > r1g) Sa[j][2] = -1e9f;
                if (c0 + 1 > r1g) Sa[j][3] = -1e9f;
            }
        }

        // ---- online softmax (register, quad-reduced) ----
        float mx0 = -1e30f, mx1 = -1e30f;
#pragma unroll
        for (int j = 0; j < 8; j++) {
            mx0 = fmaxf(mx0, fmaxf(Sa[j][0], Sa[j][1]));
            mx1 = fmaxf(mx1, fmaxf(Sa[j][2], Sa[j][3]));
        }
        mx0 = fmaxf(mx0, __shfl_xor_sync(0xffffffff, mx0, 1));
        mx0 = fmaxf(mx0, __shfl_xor_sync(0xffffffff, mx0, 2));
        mx1 = fmaxf(mx1, __shfl_xor_sync(0xffffffff, mx1, 1));
        mx1 = fmaxf(mx1, __shfl_xor_sync(0xffffffff, mx1, 2));

        const float mn0 = fmaxf(m[0], mx0);
        const float mn1 = fmaxf(m[1], mx1);
        const float alpha0 = __expf(m[0] - mn0);
        const float alpha1 = __expf(m[1] - mn1);
        m[0] = mn0; m[1] = mn1;

        float sum0 = 0.f, sum1 = 0.f;
#pragma unroll
        for (int j = 0; j < 8; j++) {
            Sa[j][0] = __expf(Sa[j][0] - mn0);
            Sa[j][1] = __expf(Sa[j][1] - mn0);
            Sa[j][2] = __expf(Sa[j][2] - mn1);
            Sa[j][3] = __expf(Sa[j][3] - mn1);
            sum0 += Sa[j][0] + Sa[j][1];
            sum1 += Sa[j][2] + Sa[j][3];
        }
        sum0 += __shfl_xor_sync(0xffffffff, sum0, 1);
        sum0 += __shfl_xor_sync(0xffffffff, sum0, 2);
        sum1 += __shfl_xor_sync(0xffffffff, sum1, 1);
        sum1 += __shfl_xor_sync(0xffffffff, sum1, 2);
        l[0] = l[0] * alpha0 + sum0;
        l[1] = l[1] * alpha1 + sum1;

#pragma unroll
        for (int nt = 0; nt < 16; nt++) {
            Oa[nt][0] *= alpha0; Oa[nt][1] *= alpha0;
            Oa[nt][2] *= alpha1; Oa[nt][3] *= alpha1;
        }

        // ---- P V (3-pass split), P from S registers ----
        const uint32_t vBase = s0 + lrow * SVB + lkoff;
#pragma unroll
        for (int ks = 0; ks < 4; ks++) {
            uint32_t ph[4], pl[4];
#pragma unroll
            for (int hf = 0; hf < 2; hf++) {
                const int j = 2 * ks + hf;
                __nv_bfloat162 h01 = __floats2bfloat162_rn(Sa[j][0], Sa[j][1]);
                __nv_bfloat162 h23 = __floats2bfloat162_rn(Sa[j][2], Sa[j][3]);
                ph[2*hf]     = *(uint32_t*)&h01;
                ph[2*hf + 1] = *(uint32_t*)&h23;
                __nv_bfloat162 l01 = __floats2bfloat162_rn(
                    Sa[j][0] - __bfloat162float(h01.x), Sa[j][1] - __bfloat162float(h01.y));
                __nv_bfloat162 l23 = __floats2bfloat162_rn(
                    Sa[j][2] - __bfloat162float(h23.x), Sa[j][3] - __bfloat162float(h23.y));
                pl[2*hf]     = *(uint32_t*)&l01;
                pl[2*hf + 1] = *(uint32_t*)&l23;
            }
#pragma unroll
            for (int nb = 0; nb < 8; nb++) {
                uint32_t vb[4];
                ldsm4(vb, vBase + AVHI + nb * 16 * SVB + ks * 32);
                mma_bf16(Oa[2*nb],   ph, vb[0], vb[2]);
                mma_bf16(Oa[2*nb+1], ph, vb[1], vb[3]);
                mma_bf16(Oa[2*nb],   pl, vb[0], vb[2]);
                mma_bf16(Oa[2*nb+1], pl, vb[1], vb[3]);
                ldsm4(vb, vBase + AVLO + nb * 16 * SVB + ks * 32);
                mma_bf16(Oa[2*nb],   ph, vb[0], vb[2]);
                mma_bf16(Oa[2*nb+1], ph, vb[1], vb[3]);
            }
        }
    }

    // ---- epilogue: normalize, split to bf16 hi/lo planes ----
    const float invl0 = 1.f / l[0];
    const float invl1 = 1.f / l[1];
    const int r0g = q0 + w * 16 + grp;
    const size_t row0 = (size_t)(b * SEQ + r0g) * DIM + h * HD;
    const size_t row1 = row0 + (size_t)8 * DIM;
#pragma unroll
    for (int nt = 0; nt < 16; nt++) {
        const int col = nt * 8 + tig * 2;
        float o0 = Oa[nt][0] * invl0, o1 = Oa[nt][1] * invl0;
        float o2 = Oa[nt][2] * invl1, o3 = Oa[nt][3] * invl1;
        __nv_bfloat162 h01 = __floats2bfloat162_rn(o0, o1);
        __nv_bfloat162 h23 = __floats2bfloat162_rn(o2, o3);
        *(__nv_bfloat162*)(Ohi + row0 + col) = h01;
        *(__nv_bfloat162*)(Ohi + row1 + col) = h23;
        __nv_bfloat162 l01 = __floats2bfloat162_rn(o0 - __bfloat162float(h01.x),
                                                   o1 - __bfloat162float(h01.y));
        __nv_bfloat162 l23 = __floats2bfloat162_rn(o2 - __bfloat162float(h23.x),
                                                   o3 - __bfloat162float(h23.y));
        *(__nv_bfloat162*)(Olo + row0 + col) = l01;
        *(__nv_bfloat162*)(Olo + row1 + col) = l23;
    }
}

// ---------------------------------------------------------------------------
extern "C" void kernel_launch(void* const* d_in, const int* in_sizes, int n_in,
                              void* d_out, int out_size)
{
    (void)in_sizes; (void)n_in; (void)out_size;
    const float* x  = (const float*)d_in[0];
    const float* Wq = (const float*)d_in[1];
    const float* Wk = (const float*)d_in[2];
    const float* Wv = (const float*)d_in[3];
    const float* Wo = (const float*)d_in[4];
    const float* bo = (const float*)d_in[5];
    float* out = (float*)d_out;

    float *q, *k, *v;
    __nv_bfloat16 *xhi, *xlo, *ahi, *alo, *whi, *wlo;
    __nv_bfloat16 *qhi, *qlo, *khi, *klo, *vhi, *vlo;
    cudaGetSymbolAddress((void**)&q,   g_q);
    cudaGetSymbolAddress((void**)&k,   g_k);
    cudaGetSymbolAddress((void**)&v,   g_v);
    cudaGetSymbolAddress((void**)&xhi, g_xhi);
    cudaGetSymbolAddress((void**)&xlo, g_xlo);
    cudaGetSymbolAddress((void**)&ahi, g_ahi);
    cudaGetSymbolAddress((void**)&alo, g_alo);
    cudaGetSymbolAddress((void**)&whi, g_whi);
    cudaGetSymbolAddress((void**)&wlo, g_wlo);
    cudaGetSymbolAddress((void**)&qhi, g_qhi);
    cudaGetSymbolAddress((void**)&qlo, g_qlo);
    cudaGetSymbolAddress((void**)&khi, g_khi);
    cudaGetSymbolAddress((void**)&klo, g_klo);
    cudaGetSymbolAddress((void**)&vhi, g_vhi);
    cudaGetSymbolAddress((void**)&vlo, g_vlo);

    const size_t WSZ = (size_t)DIM * DIM;
    const int nx4 = (MROWS * DIM) / 4;
    const int nw4 = (DIM * DIM) / 4;

    split_kernel<<<nx4 / 256, 256>>>(x, xhi, xlo, nx4);
    split_kernel<<<nw4 / 256, 256>>>(Wq, whi + 0 * WSZ, wlo + 0 * WSZ, nw4);
    split_kernel<<<nw4 / 256, 256>>>(Wk, whi + 1 * WSZ, wlo + 1 * WSZ, nw4);
    split_kernel<<<nw4 / 256, 256>>>(Wv, whi + 2 * WSZ, wlo + 2 * WSZ, nw4);
    split_kernel<<<nw4 / 256, 256>>>(Wo, whi + 3 * WSZ, wlo + 3 * WSZ, nw4);

    cudaFuncSetAttribute(gemm_mma_kernel,
                         cudaFuncAttributeMaxDynamicSharedMemorySize, GSMEM);

    dim3 ggrid(DIM / 128, MROWS / 128);
    gemm_mma_kernel<<<ggrid, 256, GSMEM>>>(xhi, xlo, whi + 0 * WSZ, wlo + 0 * WSZ,
                                           nullptr, q, MROWS, DIM, DIM);
    gemm_mma_kernel<<<ggrid, 256, GSMEM>>>(xhi, xlo, whi + 1 * WSZ, wlo + 1 * WSZ,
                                           nullptr, k, MROWS, DIM, DIM);
    gemm_mma_kernel<<<ggrid, 256, GSMEM>>>(xhi, xlo, whi + 2 * WSZ, wlo + 2 * WSZ,
                                           nullptr, v, MROWS, DIM, DIM);

    int rope_threads = BATCH * SEQ * NHEAD * 64;
    rope_split_kernel<<<rope_threads / 256, 256>>>(q, qhi, qlo);
    rope_split_kernel<<<rope_threads / 256, 256>>>(k, khi, klo);
    split_kernel<<<nx4 / 256, 256>>>(v, vhi, vlo, nx4);

    cudaFuncSetAttribute(attn_mma_kernel,
                         cudaFuncAttributeMaxDynamicSharedMemorySize, ASMEM);
    attn_mma_kernel<<<dim3(SEQ / 128, BATCH * NHEAD), 256, ASMEM>>>(
        qhi, qlo, khi, klo, vhi, vlo, ahi, alo);

    gemm_mma_kernel<<<ggrid, 256, GSMEM>>>(ahi, alo, whi + 3 * WSZ, wlo + 3 * WSZ,
                                           bo, out, MROWS, DIM, DIM);
}

// round 6
// speedup vs baseline: 3.3962x; 1.3777x over previous
#include <cuda_runtime.h>
#include <cuda_bf16.h>
#include <cuda_fp16.h>
#include <math.h>
#include <stdint.h>

#define BATCH 4
#define SEQ   2048
#define DIM   2048
#define NHEAD 16
#define HD    128
#define MROWS (BATCH*SEQ)   // 8192

// ---------------- scratch (static device globals) ----------------
__device__ float g_q[(size_t)MROWS * DIM];
__device__ float g_k[(size_t)MROWS * DIM];
__device__ float g_v[(size_t)MROWS * DIM];
// fp16 planes for projection GEMMs
__device__ __half g_xh[(size_t)MROWS * DIM];
__device__ __half g_xl[(size_t)MROWS * DIM];
__device__ __half g_ah[(size_t)MROWS * DIM];
__device__ __half g_al[(size_t)MROWS * DIM];
__device__ __half g_w16[4][(size_t)DIM * DIM];
// bf16 planes for attention (3-pass bf16 split, verified)
__device__ __nv_bfloat16 g_qhi[(size_t)MROWS * DIM];
__device__ __nv_bfloat16 g_qlo[(size_t)MROWS * DIM];
__device__ __nv_bfloat16 g_khi[(size_t)MROWS * DIM];
__device__ __nv_bfloat16 g_klo[(size_t)MROWS * DIM];
__device__ __nv_bfloat16 g_vhi[(size_t)MROWS * DIM];
__device__ __nv_bfloat16 g_vlo[(size_t)MROWS * DIM];

// ---------------- low-level helpers ----------------
__device__ __forceinline__ uint32_t smem_u32(const void* p) {
    uint32_t a;
    asm("{ .reg .u64 t; cvta.to.shared.u64 t, %1; cvt.u32.u64 %0, t; }" : "=r"(a) : "l"(p));
    return a;
}
__device__ __forceinline__ void cp_async16(uint32_t s, const void* g) {
    asm volatile("cp.async.cg.shared.global [%0], [%1], 16;" :: "r"(s), "l"(g));
}
#define CP_COMMIT()  asm volatile("cp.async.commit_group;" ::: "memory")
#define CP_WAIT(n)   asm volatile("cp.async.wait_group %0;" :: "n"(n) : "memory")

__device__ __forceinline__ void ldsm4(uint32_t* r, uint32_t addr) {
    asm volatile("ldmatrix.sync.aligned.m8n8.x4.shared.b16 {%0,%1,%2,%3}, [%4];"
                 : "=r"(r[0]), "=r"(r[1]), "=r"(r[2]), "=r"(r[3]) : "r"(addr));
}
__device__ __forceinline__ void mma_bf16(float* d, const uint32_t* a, uint32_t b0, uint32_t b1) {
    asm volatile(
        "mma.sync.aligned.m16n8k16.row.col.f32.bf16.bf16.f32 "
        "{%0,%1,%2,%3}, {%4,%5,%6,%7}, {%8,%9}, {%0,%1,%2,%3};"
        : "+f"(d[0]), "+f"(d[1]), "+f"(d[2]), "+f"(d[3])
        : "r"(a[0]), "r"(a[1]), "r"(a[2]), "r"(a[3]), "r"(b0), "r"(b1));
}
__device__ __forceinline__ void mma_f16(float* d, const uint32_t* a, uint32_t b0, uint32_t b1) {
    asm volatile(
        "mma.sync.aligned.m16n8k16.row.col.f32.f16.f16.f32 "
        "{%0,%1,%2,%3}, {%4,%5,%6,%7}, {%8,%9}, {%0,%1,%2,%3};"
        : "+f"(d[0]), "+f"(d[1]), "+f"(d[2]), "+f"(d[3])
        : "r"(a[0]), "r"(a[1]), "r"(a[2]), "r"(a[3]), "r"(b0), "r"(b1));
}

// ---------------------------------------------------------------------------
// fp32 -> fp16 (hi,lo) split.  lo = fp16(x - float(hi)).
// ---------------------------------------------------------------------------
__global__ __launch_bounds__(256)
void split16_kernel(const float* __restrict__ src, __half* __restrict__ hi,
                    __half* __restrict__ lo, int n4)
{
    int i = blockIdx.x * blockDim.x + threadIdx.x;
    if (i >= n4) return;
    float4 x = ((const float4*)src)[i];
    __half h0 = __float2half(x.x), h1 = __float2half(x.y);
    __half h2 = __float2half(x.z), h3 = __float2half(x.w);
    __half2 H0; H0.x = h0; H0.y = h1;
    __half2 H1; H1.x = h2; H1.y = h3;
    ((__half2*)hi)[i*2]   = H0;
    ((__half2*)hi)[i*2+1] = H1;
    __half2 L0, L1;
    L0.x = __float2half(x.x - __half2float(h0));
    L0.y = __float2half(x.y - __half2float(h1));
    L1.x = __float2half(x.z - __half2float(h2));
    L1.y = __float2half(x.w - __half2float(h3));
    ((__half2*)lo)[i*2]   = L0;
    ((__half2*)lo)[i*2+1] = L1;
}

// fp32 -> fp16 (round only; for weights)
__global__ __launch_bounds__(256)
void cvt16_kernel(const float* __restrict__ src, __half* __restrict__ dst, int n4)
{
    int i = blockIdx.x * blockDim.x + threadIdx.x;
    if (i >= n4) return;
    float4 x = ((const float4*)src)[i];
    __half2 H0; H0.x = __float2half(x.x); H0.y = __float2half(x.y);
    __half2 H1; H1.x = __float2half(x.z); H1.y = __float2half(x.w);
    ((__half2*)dst)[i*2]   = H0;
    ((__half2*)dst)[i*2+1] = H1;
}

// ---------------------------------------------------------------------------
// fp32 -> bf16 (hi,lo) split (attention V path)
// ---------------------------------------------------------------------------
__global__ __launch_bounds__(256)
void split_kernel(const float* __restrict__ src, __nv_bfloat16* __restrict__ hi,
                  __nv_bfloat16* __restrict__ lo, int n4)
{
    int i = blockIdx.x * blockDim.x + threadIdx.x;
    if (i >= n4) return;
    float4 x = ((const float4*)src)[i];
    __nv_bfloat16 h0 = __float2bfloat16(x.x);
    __nv_bfloat16 h1 = __float2bfloat16(x.y);
    __nv_bfloat16 h2 = __float2bfloat16(x.z);
    __nv_bfloat16 h3 = __float2bfloat16(x.w);
    __nv_bfloat162 H0; H0.x = h0; H0.y = h1;
    __nv_bfloat162 H1; H1.x = h2; H1.y = h3;
    ((__nv_bfloat162*)hi)[i*2]   = H0;
    ((__nv_bfloat162*)hi)[i*2+1] = H1;
    __nv_bfloat162 L0, L1;
    L0.x = __float2bfloat16(x.x - __bfloat162float(h0));
    L0.y = __float2bfloat16(x.y - __bfloat162float(h1));
    L1.x = __float2bfloat16(x.z - __bfloat162float(h2));
    L1.y = __float2bfloat16(x.w - __bfloat162float(h3));
    ((__nv_bfloat162*)lo)[i*2]   = L0;
    ((__nv_bfloat162*)lo)[i*2+1] = L1;
}

// ---------------------------------------------------------------------------
// Fused RoPE + bf16 split
// ---------------------------------------------------------------------------
__global__ __launch_bounds__(256)
void rope_split_kernel(const float* __restrict__ src,
                       __nv_bfloat16* __restrict__ hi, __nv_bfloat16* __restrict__ lo)
{
    int idx = blockIdx.x * blockDim.x + threadIdx.x;
    int i = idx & 63;
    int h = (idx >> 6) & (NHEAD - 1);
    int s = (idx >> 10) & (SEQ - 1);
    int b = idx >> 21;

    float inv = expf(-9.210340371976184f * ((float)i * (1.0f / 64.0f)));
    float ang = (float)s * inv;
    float c, sn;
    sincosf(ang, &sn, &c);

    size_t base = (size_t)(b * SEQ + s) * DIM + h * HD;
    float t1 = src[base + i];
    float t2 = src[base + i + 64];
    float o1 = t1 * c - t2 * sn;
    float o2 = t2 * c + t1 * sn;

    __nv_bfloat16 h1 = __float2bfloat16(o1);
    __nv_bfloat16 h2 = __float2bfloat16(o2);
    hi[base + i]      = h1;
    hi[base + i + 64] = h2;
    lo[base + i]      = __float2bfloat16(o1 - __bfloat162float(h1));
    lo[base + i + 64] = __float2bfloat16(o2 - __bfloat162float(h2));
}

// ---------------------------------------------------------------------------
// fp16 2-pass GEMM via mma.sync:
//   C[M,N] = (Ah+Al)[M,K] * Bh[N,K]^T (+bias)
// CTA tile 128x128, BK=32, 8 warps (32x64 each), 3-stage cp.async pipeline.
// ---------------------------------------------------------------------------
#define GBK       32
#define ROW_B     80
#define PLANE_B   (128 * ROW_B)        // 10240
#define STAGE_B   (3 * PLANE_B)        // 30720 (Ah, Al, Bh)
#define NSTAGE    3
#define GSMEM     (NSTAGE * STAGE_B)   // 92160

__device__ __forceinline__ void load_stage(uint32_t st_u32,
    const __half* __restrict__ Ah, const __half* __restrict__ Al,
    const __half* __restrict__ Bh,
    int m0, int n0, int K, int kc, int tid)
{
#pragma unroll
    for (int p = 0; p < 3; p++) {
        const __half* src = (p == 0) ? Ah : (p == 1) ? Al : Bh;
        const int rbase = (p < 2) ? m0 : n0;
#pragma unroll
        for (int i = 0; i < 2; i++) {
            int idx = i * 256 + tid;
            int r = idx >> 2, c = idx & 3;
            const void* g = src + (size_t)(rbase + r) * K + kc + c * 8;
            cp_async16(st_u32 + p * PLANE_B + r * ROW_B + c * 16, g);
        }
    }
}

__global__ __launch_bounds__(256, 1)
void gemm_mma_kernel(const __half* __restrict__ Ah, const __half* __restrict__ Al,
                     const __half* __restrict__ Bh,
                     const float* __restrict__ bias, float* __restrict__ C,
                     int M, int N, int K)
{
    extern __shared__ char smem[];
    const uint32_t sm0 = smem_u32(smem);
    const int tid  = threadIdx.x;
    const int wid  = tid >> 5;
    const int lane = tid & 31;
    const int wm   = wid & 3;
    const int wn   = wid >> 2;
    const int m0 = blockIdx.y * 128;
    const int n0 = blockIdx.x * 128;
    const int nchunk = K / GBK;

    float acc[2][8][4];
#pragma unroll
    for (int mt = 0; mt < 2; mt++)
#pragma unroll
        for (int nt = 0; nt < 8; nt++)
#pragma unroll
            for (int q = 0; q < 4; q++) acc[mt][nt][q] = 0.f;

    const int lrow  = lane & 15;
    const int lkoff = (lane >> 4) * 16;

    load_stage(sm0,           Ah, Al, Bh, m0, n0, K, 0,   tid);
    CP_COMMIT();
    load_stage(sm0 + STAGE_B, Ah, Al, Bh, m0, n0, K, GBK, tid);
    CP_COMMIT();

    for (int i = 0; i < nchunk; i++) {
        CP_WAIT(1);
        __syncthreads();

        if (i + 2 < nchunk)
            load_stage(sm0 + ((i + 2) % NSTAGE) * STAGE_B,
                       Ah, Al, Bh, m0, n0, K, (i + 2) * GBK, tid);
        CP_COMMIT();

        const uint32_t st = sm0 + (i % NSTAGE) * STAGE_B;
        const uint32_t aRow = st + (wm * 32 + lrow) * ROW_B + lkoff;
        const uint32_t bRow = st + 2 * PLANE_B + (wn * 64 + lrow) * ROW_B + lkoff;

#pragma unroll
        for (int ks = 0; ks < 2; ks++) {
            uint32_t ah[2][4], al[2][4], bh[4][4];
#pragma unroll
            for (int mt = 0; mt < 2; mt++) {
                ldsm4(ah[mt], aRow           + mt * (16 * ROW_B) + ks * 32);
                ldsm4(al[mt], aRow + PLANE_B + mt * (16 * ROW_B) + ks * 32);
            }
#pragma unroll
            for (int np = 0; np < 4; np++)
                ldsm4(bh[np], bRow + np * (16 * ROW_B) + ks * 32);
#pragma unroll
            for (int mt = 0; mt < 2; mt++)
#pragma unroll
                for (int nt = 0; nt < 8; nt++) {
                    const int np = nt >> 1, h = nt & 1;
                    mma_f16(acc[mt][nt], ah[mt], bh[np][h], bh[np][2 + h]);
                    mma_f16(acc[mt][nt], al[mt], bh[np][h], bh[np][2 + h]);
                }
        }
        __syncthreads();
    }

    const int grp = lane >> 2;
    const int tig = lane & 3;
#pragma unroll
    for (int mt = 0; mt < 2; mt++) {
        const int rbase = m0 + wm * 32 + mt * 16 + grp;
#pragma unroll
        for (int nt = 0; nt < 8; nt++) {
            const int col = n0 + wn * 64 + nt * 8 + tig * 2;
            float bx = 0.f, by = 0.f;
            if (bias) { bx = bias[col]; by = bias[col + 1]; }
            float2 v0; v0.x = acc[mt][nt][0] + bx; v0.y = acc[mt][nt][1] + by;
            float2 v1; v1.x = acc[mt][nt][2] + bx; v1.y = acc[mt][nt][3] + by;
            *(float2*)(C + (size_t)rbase * N + col)       = v0;
            *(float2*)(C + (size_t)(rbase + 8) * N + col) = v1;
        }
    }
}

// ---------------------------------------------------------------------------
// Causal flash attention via mma.sync bf16-split (3-pass, verified in R5).
// Epilogue writes fp16 hi/lo planes for the Wo projection.
// ---------------------------------------------------------------------------
#define SKB 272
#define SVB 144
#define AQHI 0
#define AQLO (AQHI + 128*SKB)
#define AKHI (AQLO + 128*SKB)
#define AKLO (AKHI + 64*SKB)
#define AVHI (AKLO + 64*SKB)
#define AVLO (AVHI + 128*SVB)
#define ASMEM (AVLO + 128*SVB)   // 141312

__global__ __launch_bounds__(256, 1)
void attn_mma_kernel(const __nv_bfloat16* __restrict__ Qhi, const __nv_bfloat16* __restrict__ Qlo,
                     const __nv_bfloat16* __restrict__ Khi, const __nv_bfloat16* __restrict__ Klo,
                     const __nv_bfloat16* __restrict__ Vhi, const __nv_bfloat16* __restrict__ Vlo,
                     __half* __restrict__ Ohi, __half* __restrict__ Olo)
{
    extern __shared__ char smem[];
    const uint32_t s0 = smem_u32(smem);
    const int tid  = threadIdx.x;
    const int w    = tid >> 5;
    const int lane = tid & 31;
    const int grp  = lane >> 2;
    const int tig  = lane & 3;
    const int lrow  = lane & 15;
    const int lkoff = (lane >> 4) * 16;

    const int bh = blockIdx.y;
    const int b  = bh >> 4;
    const int h  = bh & (NHEAD - 1);
    const int qt = blockIdx.x;
    const int q0 = qt * 128;

    const size_t rowQ = (size_t)(b * SEQ + q0);
    const __nv_bfloat16* qh_g = Qhi + rowQ * DIM + h * HD;
    const __nv_bfloat16* ql_g = Qlo + rowQ * DIM + h * HD;

#pragma unroll
    for (int u = 0; u < 8; u++) {
        int idx = u * 256 + tid;
        int r = idx >> 4, c = idx & 15;
        cp_async16(s0 + AQHI + r * SKB + c * 16, qh_g + (size_t)r * DIM + c * 8);
        cp_async16(s0 + AQLO + r * SKB + c * 16, ql_g + (size_t)r * DIM + c * 8);
    }
    CP_COMMIT();

    float m[2] = {-1e30f, -1e30f};
    float l[2] = {0.f, 0.f};
    float Oa[16][4];
#pragma unroll
    for (int nt = 0; nt < 16; nt++)
#pragma unroll
        for (int q = 0; q < 4; q++) Oa[nt][q] = 0.f;

    const float scale = 0.08838834764831845f;
    const int nkt = 2 * qt + 2;

    for (int kt = 0; kt < nkt; kt++) {
        const int kv0 = kt * 64;
        const size_t rowK = (size_t)(b * SEQ + kv0);
        const __nv_bfloat16* kh_g = Khi + rowK * DIM + h * HD;
        const __nv_bfloat16* kl_g = Klo + rowK * DIM + h * HD;
        const __nv_bfloat16* vh_g = Vhi + rowK * DIM + h * HD;
        const __nv_bfloat16* vl_g = Vlo + rowK * DIM + h * HD;

        __syncthreads();

#pragma unroll
        for (int u = 0; u < 4; u++) {
            int idx = u * 256 + tid;
            int r = idx >> 4, c = idx & 15;
            cp_async16(s0 + AKHI + r * SKB + c * 16, kh_g + (size_t)r * DIM + c * 8);
            cp_async16(s0 + AKLO + r * SKB + c * 16, kl_g + (size_t)r * DIM + c * 8);
        }
        CP_COMMIT();

#pragma unroll
        for (int u = 0; u < 4; u++) {
            int idx = u * 256 + tid;
            int kv = idx & 63, c = idx >> 6;
            uint4 xh = *(const uint4*)(vh_g + (size_t)kv * DIM + c * 8);
            uint4 xl = *(const uint4*)(vl_g + (size_t)kv * DIM + c * 8);
            const uint16_t* uh = (const uint16_t*)&xh;
            const uint16_t* ul = (const uint16_t*)&xl;
#pragma unroll
            for (int j = 0; j < 8; j++) {
                *(uint16_t*)(smem + AVHI + (c * 8 + j) * SVB + kv * 2) = uh[j];
                *(uint16_t*)(smem + AVLO + (c * 8 + j) * SVB + kv * 2) = ul[j];
            }
        }
        CP_WAIT(0);
        __syncthreads();

        // ---- S = Q K^T (3-pass split) ----
        float Sa[8][4];
#pragma unroll
        for (int j = 0; j < 8; j++)
#pragma unroll
            for (int q = 0; q < 4; q++) Sa[j][q] = 0.f;

        const uint32_t aBase = s0 + (w * 16 + lrow) * SKB + lkoff;
        const uint32_t kBase = s0 + lrow * SKB + lkoff;
#pragma unroll
        for (int ks = 0; ks < 8; ks++) {
            uint32_t ah[4], al[4];
            ldsm4(ah, aBase + AQHI + ks * 32);
            ldsm4(al, aBase + AQLO + ks * 32);
#pragma unroll
            for (int p = 0; p < 4; p++) {
                uint32_t kb[4];
                ldsm4(kb, kBase + AKHI + p * 16 * SKB + ks * 32);
                mma_bf16(Sa[2*p],   ah, kb[0], kb[2]);
                mma_bf16(Sa[2*p+1], ah, kb[1], kb[3]);
                mma_bf16(Sa[2*p],   al, kb[0], kb[2]);
                mma_bf16(Sa[2*p+1], al, kb[1], kb[3]);
                ldsm4(kb, kBase + AKLO + p * 16 * SKB + ks * 32);
                mma_bf16(Sa[2*p],   ah, kb[0], kb[2]);
                mma_bf16(Sa[2*p+1], ah, kb[1], kb[3]);
            }
        }

        // ---- scale + causal mask ----
        const int r0g = q0 + w * 16 + grp;
        const int r1g = r0g + 8;
        const bool need_mask = (kt >= 2 * qt);
#pragma unroll
        for (int j = 0; j < 8; j++) {
            const int c0 = kv0 + j * 8 + tig * 2;
            Sa[j][0] *= scale; Sa[j][1] *= scale;
            Sa[j][2] *= scale; Sa[j][3] *= scale;
            if (need_mask) {
                if (c0     > r0g) Sa[j][0] = -1e9f;
                if (c0 + 1 > r0g) Sa[j][1] = -1e9f;
                if (c0     > r1g) Sa[j][2] = -1e9f;
                if (c0 + 1 > r1g) Sa[j][3] = -1e9f;
            }
        }

        // ---- online softmax ----
        float mx0 = -1e30f, mx1 = -1e30f;
#pragma unroll
        for (int j = 0; j < 8; j++) {
            mx0 = fmaxf(mx0, fmaxf(Sa[j][0], Sa[j][1]));
            mx1 = fmaxf(mx1, fmaxf(Sa[j][2], Sa[j][3]));
        }
        mx0 = fmaxf(mx0, __shfl_xor_sync(0xffffffff, mx0, 1));
        mx0 = fmaxf(mx0, __shfl_xor_sync(0xffffffff, mx0, 2));
        mx1 = fmaxf(mx1, __shfl_xor_sync(0xffffffff, mx1, 1));
        mx1 = fmaxf(mx1, __shfl_xor_sync(0xffffffff, mx1, 2));

        const float mn0 = fmaxf(m[0], mx0);
        const float mn1 = fmaxf(m[1], mx1);
        const float alpha0 = __expf(m[0] - mn0);
        const float alpha1 = __expf(m[1] - mn1);
        m[0] = mn0; m[1] = mn1;

        float sum0 = 0.f, sum1 = 0.f;
#pragma unroll
        for (int j = 0; j < 8; j++) {
            Sa[j][0] = __expf(Sa[j][0] - mn0);
            Sa[j][1] = __expf(Sa[j][1] - mn0);
            Sa[j][2] = __expf(Sa[j][2] - mn1);
            Sa[j][3] = __expf(Sa[j][3] - mn1);
            sum0 += Sa[j][0] + Sa[j][1];
            sum1 += Sa[j][2] + Sa[j][3];
        }
        sum0 += __shfl_xor_sync(0xffffffff, sum0, 1);
        sum0 += __shfl_xor_sync(0xffffffff, sum0, 2);
        sum1 += __shfl_xor_sync(0xffffffff, sum1, 1);
        sum1 += __shfl_xor_sync(0xffffffff, sum1, 2);
        l[0] = l[0] * alpha0 + sum0;
        l[1] = l[1] * alpha1 + sum1;

#pragma unroll
        for (int nt = 0; nt < 16; nt++) {
            Oa[nt][0] *= alpha0; Oa[nt][1] *= alpha0;
            Oa[nt][2] *= alpha1; Oa[nt][3] *= alpha1;
        }

        // ---- P V (3-pass split) ----
        const uint32_t vBase = s0 + lrow * SVB + lkoff;
#pragma unroll
        for (int ks = 0; ks < 4; ks++) {
            uint32_t ph[4], pl[4];
#pragma unroll
            for (int hf = 0; hf < 2; hf++) {
                const int j = 2 * ks + hf;
                __nv_bfloat162 h01 = __floats2bfloat162_rn(Sa[j][0], Sa[j][1]);
                __nv_bfloat162 h23 = __floats2bfloat162_rn(Sa[j][2], Sa[j][3]);
                ph[2*hf]     = *(uint32_t*)&h01;
                ph[2*hf + 1] = *(uint32_t*)&h23;
                __nv_bfloat162 l01 = __floats2bfloat162_rn(
                    Sa[j][0] - __bfloat162float(h01.x), Sa[j][1] - __bfloat162float(h01.y));
                __nv_bfloat162 l23 = __floats2bfloat162_rn(
                    Sa[j][2] - __bfloat162float(h23.x), Sa[j][3] - __bfloat162float(h23.y));
                pl[2*hf]     = *(uint32_t*)&l01;
                pl[2*hf + 1] = *(uint32_t*)&l23;
            }
#pragma unroll
            for (int nb = 0; nb < 8; nb++) {
                uint32_t vb[4];
                ldsm4(vb, vBase + AVHI + nb * 16 * SVB + ks * 32);
                mma_bf16(Oa[2*nb],   ph, vb[0], vb[2]);
                mma_bf16(Oa[2*nb+1], ph, vb[1], vb[3]);
                mma_bf16(Oa[2*nb],   pl, vb[0], vb[2]);
                mma_bf16(Oa[2*nb+1], pl, vb[1], vb[3]);
                ldsm4(vb, vBase + AVLO + nb * 16 * SVB + ks * 32);
                mma_bf16(Oa[2*nb],   ph, vb[0], vb[2]);
                mma_bf16(Oa[2*nb+1], ph, vb[1], vb[3]);
            }
        }
    }

    // ---- epilogue: normalize, write fp16 hi/lo planes ----
    const float invl0 = 1.f / l[0];
    const float invl1 = 1.f / l[1];
    const int r0g = q0 + w * 16 + grp;
    const size_t row0 = (size_t)(b * SEQ + r0g) * DIM + h * HD;
    const size_t row1 = row0 + (size_t)8 * DIM;
#pragma unroll
    for (int nt = 0; nt < 16; nt++) {
        const int col = nt * 8 + tig * 2;
        float o0 = Oa[nt][0] * invl0, o1 = Oa[nt][1] * invl0;
        float o2 = Oa[nt][2] * invl1, o3 = Oa[nt][3] * invl1;
        __half2 h01 = __floats2half2_rn(o0, o1);
        __half2 h23 = __floats2half2_rn(o2, o3);
        *(__half2*)(Ohi + row0 + col) = h01;
        *(__half2*)(Ohi + row1 + col) = h23;
        __half2 l01 = __floats2half2_rn(o0 - __half2float(h01.x),
                                        o1 - __half2float(h01.y));
        __half2 l23 = __floats2half2_rn(o2 - __half2float(h23.x),
                                        o3 - __half2float(h23.y));
        *(__half2*)(Olo + row0 + col) = l01;
        *(__half2*)(Olo + row1 + col) = l23;
    }
}

// ---------------------------------------------------------------------------
extern "C" void kernel_launch(void* const* d_in, const int* in_sizes, int n_in,
                              void* d_out, int out_size)
{
    (void)in_sizes; (void)n_in; (void)out_size;
    const float* x  = (const float*)d_in[0];
    const float* Wq = (const float*)d_in[1];
    const float* Wk = (const float*)d_in[2];
    const float* Wv = (const float*)d_in[3];
    const float* Wo = (const float*)d_in[4];
    const float* bo = (const float*)d_in[5];
    float* out = (float*)d_out;

    float *q, *k, *v;
    __half *xh, *xl, *ah, *al, *w16;
    __nv_bfloat16 *qhi, *qlo, *khi, *klo, *vhi, *vlo;
    cudaGetSymbolAddress((void**)&q,   g_q);
    cudaGetSymbolAddress((void**)&k,   g_k);
    cudaGetSymbolAddress((void**)&v,   g_v);
    cudaGetSymbolAddress((void**)&xh,  g_xh);
    cudaGetSymbolAddress((void**)&xl,  g_xl);
    cudaGetSymbolAddress((void**)&ah,  g_ah);
    cudaGetSymbolAddress((void**)&al,  g_al);
    cudaGetSymbolAddress((void**)&w16, g_w16);
    cudaGetSymbolAddress((void**)&qhi, g_qhi);
    cudaGetSymbolAddress((void**)&qlo, g_qlo);
    cudaGetSymbolAddress((void**)&khi, g_khi);
    cudaGetSymbolAddress((void**)&klo, g_klo);
    cudaGetSymbolAddress((void**)&vhi, g_vhi);
    cudaGetSymbolAddress((void**)&vlo, g_vlo);

    const size_t WSZ = (size_t)DIM * DIM;
    const int nx4 = (MROWS * DIM) / 4;
    const int nw4 = (DIM * DIM) / 4;

    split16_kernel<<<nx4 / 256, 256>>>(x, xh, xl, nx4);
    cvt16_kernel<<<nw4 / 256, 256>>>(Wq, w16 + 0 * WSZ, nw4);
    cvt16_kernel<<<nw4 / 256, 256>>>(Wk, w16 + 1 * WSZ, nw4);
    cvt16_kernel<<<nw4 / 256, 256>>>(Wv, w16 + 2 * WSZ, nw4);
    cvt16_kernel<<<nw4 / 256, 256>>>(Wo, w16 + 3 * WSZ, nw4);

    cudaFuncSetAttribute(gemm_mma_kernel,
                         cudaFuncAttributeMaxDynamicSharedMemorySize, GSMEM);

    dim3 ggrid(DIM / 128, MROWS / 128);
    gemm_mma_kernel<<<ggrid, 256, GSMEM>>>(xh, xl, w16 + 0 * WSZ, nullptr, q, MROWS, DIM, DIM);
    gemm_mma_kernel<<<ggrid, 256, GSMEM>>>(xh, xl, w16 + 1 * WSZ, nullptr, k, MROWS, DIM, DIM);
    gemm_mma_kernel<<<ggrid, 256, GSMEM>>>(xh, xl, w16 + 2 * WSZ, nullptr, v, MROWS, DIM, DIM);

    int rope_threads = BATCH * SEQ * NHEAD * 64;
    rope_split_kernel<<<rope_threads / 256, 256>>>(q, qhi, qlo);
    rope_split_kernel<<<rope_threads / 256, 256>>>(k, khi, klo);
    split_kernel<<<nx4 / 256, 256>>>(v, vhi, vlo, nx4);

    cudaFuncSetAttribute(attn_mma_kernel,
                         cudaFuncAttributeMaxDynamicSharedMemorySize, ASMEM);
    attn_mma_kernel<<<dim3(SEQ / 128, BATCH * NHEAD), 256, ASMEM>>>(
        qhi, qlo, khi, klo, vhi, vlo, ah, al);

    gemm_mma_kernel<<<ggrid, 256, GSMEM>>>(ah, al, w16 + 3 * WSZ, bo, out, MROWS, DIM, DIM);
}

// round 7
// speedup vs baseline: 3.7643x; 1.1084x over previous
#include <cuda_runtime.h>
#include <cuda_fp16.h>
#include <math.h>
#include <stdint.h>

#define BATCH 4
#define SEQ   2048
#define DIM   2048
#define NHEAD 16
#define HD    128
#define MROWS (BATCH*SEQ)   // 8192

// ---------------- scratch (static device globals) ----------------
__device__ float g_q[(size_t)MROWS * DIM];
__device__ float g_k[(size_t)MROWS * DIM];
__device__ float g_v[(size_t)MROWS * DIM];
__device__ __half g_xh[(size_t)MROWS * DIM];
__device__ __half g_xl[(size_t)MROWS * DIM];
__device__ __half g_ah[(size_t)MROWS * DIM];
__device__ __half g_al[(size_t)MROWS * DIM];
__device__ __half g_w16[4][(size_t)DIM * DIM];
__device__ __half g_qh[(size_t)MROWS * DIM];
__device__ __half g_ql[(size_t)MROWS * DIM];
__device__ __half g_kh[(size_t)MROWS * DIM];
__device__ __half g_vh[(size_t)MROWS * DIM];

// ---------------- low-level helpers ----------------
__device__ __forceinline__ uint32_t smem_u32(const void* p) {
    uint32_t a;
    asm("{ .reg .u64 t; cvta.to.shared.u64 t, %1; cvt.u32.u64 %0, t; }" : "=r"(a) : "l"(p));
    return a;
}
__device__ __forceinline__ void cp_async16(uint32_t s, const void* g) {
    asm volatile("cp.async.cg.shared.global [%0], [%1], 16;" :: "r"(s), "l"(g));
}
#define CP_COMMIT()  asm volatile("cp.async.commit_group;" ::: "memory")
#define CP_WAIT(n)   asm volatile("cp.async.wait_group %0;" :: "n"(n) : "memory")

__device__ __forceinline__ void ldsm4(uint32_t* r, uint32_t addr) {
    asm volatile("ldmatrix.sync.aligned.m8n8.x4.shared.b16 {%0,%1,%2,%3}, [%4];"
                 : "=r"(r[0]), "=r"(r[1]), "=r"(r[2]), "=r"(r[3]) : "r"(addr));
}
__device__ __forceinline__ void mma_f16(float* d, const uint32_t* a, uint32_t b0, uint32_t b1) {
    asm volatile(
        "mma.sync.aligned.m16n8k16.row.col.f32.f16.f16.f32 "
        "{%0,%1,%2,%3}, {%4,%5,%6,%7}, {%8,%9}, {%0,%1,%2,%3};"
        : "+f"(d[0]), "+f"(d[1]), "+f"(d[2]), "+f"(d[3])
        : "r"(a[0]), "r"(a[1]), "r"(a[2]), "r"(a[3]), "r"(b0), "r"(b1));
}

// ---------------------------------------------------------------------------
// fp32 -> fp16 (hi,lo) split.
// ---------------------------------------------------------------------------
__global__ __launch_bounds__(256)
void split16_kernel(const float* __restrict__ src, __half* __restrict__ hi,
                    __half* __restrict__ lo, int n4)
{
    int i = blockIdx.x * blockDim.x + threadIdx.x;
    if (i >= n4) return;
    float4 x = ((const float4*)src)[i];
    __half h0 = __float2half(x.x), h1 = __float2half(x.y);
    __half h2 = __float2half(x.z), h3 = __float2half(x.w);
    __half2 H0; H0.x = h0; H0.y = h1;
    __half2 H1; H1.x = h2; H1.y = h3;
    ((__half2*)hi)[i*2]   = H0;
    ((__half2*)hi)[i*2+1] = H1;
    __half2 L0, L1;
    L0.x = __float2half(x.x - __half2float(h0));
    L0.y = __float2half(x.y - __half2float(h1));
    L1.x = __float2half(x.z - __half2float(h2));
    L1.y = __float2half(x.w - __half2float(h3));
    ((__half2*)lo)[i*2]   = L0;
    ((__half2*)lo)[i*2+1] = L1;
}

// fp32 -> fp16 round only
__global__ __launch_bounds__(256)
void cvt16_kernel(const float* __restrict__ src, __half* __restrict__ dst, int n4)
{
    int i = blockIdx.x * blockDim.x + threadIdx.x;
    if (i >= n4) return;
    float4 x = ((const float4*)src)[i];
    __half2 H0; H0.x = __float2half(x.x); H0.y = __float2half(x.y);
    __half2 H1; H1.x = __float2half(x.z); H1.y = __float2half(x.w);
    ((__half2*)dst)[i*2]   = H0;
    ((__half2*)dst)[i*2+1] = H1;
}

// ---------------------------------------------------------------------------
// Fused RoPE + fp16 split (Q path)
// ---------------------------------------------------------------------------
__global__ __launch_bounds__(256)
void rope_split16_kernel(const float* __restrict__ src,
                         __half* __restrict__ hi, __half* __restrict__ lo)
{
    int idx = blockIdx.x * blockDim.x + threadIdx.x;
    int i = idx & 63;
    int h = (idx >> 6) & (NHEAD - 1);
    int s = (idx >> 10) & (SEQ - 1);
    int b = idx >> 21;

    float inv = expf(-9.210340371976184f * ((float)i * (1.0f / 64.0f)));
    float ang = (float)s * inv;
    float c, sn;
    sincosf(ang, &sn, &c);

    size_t base = (size_t)(b * SEQ + s) * DIM + h * HD;
    float t1 = src[base + i];
    float t2 = src[base + i + 64];
    float o1 = t1 * c - t2 * sn;
    float o2 = t2 * c + t1 * sn;

    __half h1 = __float2half(o1);
    __half h2 = __float2half(o2);
    hi[base + i]      = h1;
    hi[base + i + 64] = h2;
    lo[base + i]      = __float2half(o1 - __half2float(h1));
    lo[base + i + 64] = __float2half(o2 - __half2float(h2));
}

// Fused RoPE + fp16 round (K path, single plane)
__global__ __launch_bounds__(256)
void rope_cvt16_kernel(const float* __restrict__ src, __half* __restrict__ dst)
{
    int idx = blockIdx.x * blockDim.x + threadIdx.x;
    int i = idx & 63;
    int h = (idx >> 6) & (NHEAD - 1);
    int s = (idx >> 10) & (SEQ - 1);
    int b = idx >> 21;

    float inv = expf(-9.210340371976184f * ((float)i * (1.0f / 64.0f)));
    float ang = (float)s * inv;
    float c, sn;
    sincosf(ang, &sn, &c);

    size_t base = (size_t)(b * SEQ + s) * DIM + h * HD;
    float t1 = src[base + i];
    float t2 = src[base + i + 64];
    dst[base + i]      = __float2half(t1 * c - t2 * sn);
    dst[base + i + 64] = __float2half(t2 * c + t1 * sn);
}

// ---------------------------------------------------------------------------
// fp16 2-pass GEMM via mma.sync; now 2 CTAs/SM.
// ---------------------------------------------------------------------------
#define GBK       32
#define ROW_B     80
#define PLANE_B   (128 * ROW_B)        // 10240
#define STAGE_B   (3 * PLANE_B)        // 30720 (Ah, Al, Bh)
#define NSTAGE    3
#define GSMEM     (NSTAGE * STAGE_B)   // 92160

__device__ __forceinline__ void load_stage(uint32_t st_u32,
    const __half* __restrict__ Ah, const __half* __restrict__ Al,
    const __half* __restrict__ Bh,
    int m0, int n0, int K, int kc, int tid)
{
#pragma unroll
    for (int p = 0; p < 3; p++) {
        const __half* src = (p == 0) ? Ah : (p == 1) ? Al : Bh;
        const int rbase = (p < 2) ? m0 : n0;
#pragma unroll
        for (int i = 0; i < 2; i++) {
            int idx = i * 256 + tid;
            int r = idx >> 2, c = idx & 3;
            const void* g = src + (size_t)(rbase + r) * K + kc + c * 8;
            cp_async16(st_u32 + p * PLANE_B + r * ROW_B + c * 16, g);
        }
    }
}

__global__ __launch_bounds__(256, 2)
void gemm_mma_kernel(const __half* __restrict__ Ah, const __half* __restrict__ Al,
                     const __half* __restrict__ Bh,
                     const float* __restrict__ bias, float* __restrict__ C,
                     int M, int N, int K)
{
    extern __shared__ char smem[];
    const uint32_t sm0 = smem_u32(smem);
    const int tid  = threadIdx.x;
    const int wid  = tid >> 5;
    const int lane = tid & 31;
    const int wm   = wid & 3;
    const int wn   = wid >> 2;
    const int m0 = blockIdx.y * 128;
    const int n0 = blockIdx.x * 128;
    const int nchunk = K / GBK;

    float acc[2][8][4];
#pragma unroll
    for (int mt = 0; mt < 2; mt++)
#pragma unroll
        for (int nt = 0; nt < 8; nt++)
#pragma unroll
            for (int q = 0; q < 4; q++) acc[mt][nt][q] = 0.f;

    const int lrow  = lane & 15;
    const int lkoff = (lane >> 4) * 16;

    load_stage(sm0,           Ah, Al, Bh, m0, n0, K, 0,   tid);
    CP_COMMIT();
    load_stage(sm0 + STAGE_B, Ah, Al, Bh, m0, n0, K, GBK, tid);
    CP_COMMIT();

    for (int i = 0; i < nchunk; i++) {
        CP_WAIT(1);
        __syncthreads();

        if (i + 2 < nchunk)
            load_stage(sm0 + ((i + 2) % NSTAGE) * STAGE_B,
                       Ah, Al, Bh, m0, n0, K, (i + 2) * GBK, tid);
        CP_COMMIT();

        const uint32_t st = sm0 + (i % NSTAGE) * STAGE_B;
        const uint32_t aRow = st + (wm * 32 + lrow) * ROW_B + lkoff;
        const uint32_t bRow = st + 2 * PLANE_B + (wn * 64 + lrow) * ROW_B + lkoff;

#pragma unroll
        for (int ks = 0; ks < 2; ks++) {
            uint32_t ah[2][4], al[2][4], bh[4][4];
#pragma unroll
            for (int mt = 0; mt < 2; mt++) {
                ldsm4(ah[mt], aRow           + mt * (16 * ROW_B) + ks * 32);
                ldsm4(al[mt], aRow + PLANE_B + mt * (16 * ROW_B) + ks * 32);
            }
#pragma unroll
            for (int np = 0; np < 4; np++)
                ldsm4(bh[np], bRow + np * (16 * ROW_B) + ks * 32);
#pragma unroll
            for (int mt = 0; mt < 2; mt++)
#pragma unroll
                for (int nt = 0; nt < 8; nt++) {
                    const int np = nt >> 1, h = nt & 1;
                    mma_f16(acc[mt][nt], ah[mt], bh[np][h], bh[np][2 + h]);
                    mma_f16(acc[mt][nt], al[mt], bh[np][h], bh[np][2 + h]);
                }
        }
        __syncthreads();
    }

    const int grp = lane >> 2;
    const int tig = lane & 3;
#pragma unroll
    for (int mt = 0; mt < 2; mt++) {
        const int rbase = m0 + wm * 32 + mt * 16 + grp;
#pragma unroll
        for (int nt = 0; nt < 8; nt++) {
            const int col = n0 + wn * 64 + nt * 8 + tig * 2;
            float bx = 0.f, by = 0.f;
            if (bias) { bx = bias[col]; by = bias[col + 1]; }
            float2 v0; v0.x = acc[mt][nt][0] + bx; v0.y = acc[mt][nt][1] + by;
            float2 v1; v1.x = acc[mt][nt][2] + bx; v1.y = acc[mt][nt][3] + by;
            *(float2*)(C + (size_t)rbase * N + col)       = v0;
            *(float2*)(C + (size_t)(rbase + 8) * N + col) = v1;
        }
    }
}

// ---------------------------------------------------------------------------
// Causal flash attention, fp16 2-pass:
//   S = (Qh+Ql) K16^T ;  O = (Ph+Pl) V16
// CTA: 128 q x 64 k per iter, 8 warps. Writes fp16 hi/lo output planes.
// ---------------------------------------------------------------------------
#define SKB 272            // Q/K smem row bytes (128 fp16 = 256B + 16 pad)
#define SVB 144            // Vt smem row bytes (64 fp16 = 128B + 16 pad)
#define AQH 0
#define AQL (AQH + 128*SKB)
#define AKH (AQL + 128*SKB)
#define AVT (AKH + 64*SKB)
#define ASMEM (AVT + 128*SVB)   // 105472

__global__ __launch_bounds__(256, 1)
void attn_mma_kernel(const __half* __restrict__ Qh, const __half* __restrict__ Ql,
                     const __half* __restrict__ Kh, const __half* __restrict__ Vh,
                     __half* __restrict__ Ohi, __half* __restrict__ Olo)
{
    extern __shared__ char smem[];
    const uint32_t s0 = smem_u32(smem);
    const int tid  = threadIdx.x;
    const int w    = tid >> 5;
    const int lane = tid & 31;
    const int grp  = lane >> 2;
    const int tig  = lane & 3;
    const int lrow  = lane & 15;
    const int lkoff = (lane >> 4) * 16;

    const int bh = blockIdx.y;
    const int b  = bh >> 4;
    const int h  = bh & (NHEAD - 1);
    const int qt = blockIdx.x;
    const int q0 = qt * 128;

    const size_t rowQ = (size_t)(b * SEQ + q0);
    const __half* qh_g = Qh + rowQ * DIM + h * HD;
    const __half* ql_g = Ql + rowQ * DIM + h * HD;

    // Q tile -> smem (both planes)
#pragma unroll
    for (int u = 0; u < 8; u++) {
        int idx = u * 256 + tid;
        int r = idx >> 4, c = idx & 15;
        cp_async16(s0 + AQH + r * SKB + c * 16, qh_g + (size_t)r * DIM + c * 8);
        cp_async16(s0 + AQL + r * SKB + c * 16, ql_g + (size_t)r * DIM + c * 8);
    }
    CP_COMMIT();

    float m[2] = {-1e30f, -1e30f};
    float l[2] = {0.f, 0.f};
    float Oa[16][4];
#pragma unroll
    for (int nt = 0; nt < 16; nt++)
#pragma unroll
        for (int q = 0; q < 4; q++) Oa[nt][q] = 0.f;

    const float scale = 0.08838834764831845f;
    const int nkt = 2 * qt + 2;

    for (int kt = 0; kt < nkt; kt++) {
        const int kv0 = kt * 64;
        const size_t rowK = (size_t)(b * SEQ + kv0);
        const __half* kh_g = Kh + rowK * DIM + h * HD;
        const __half* vh_g = Vh + rowK * DIM + h * HD;

        __syncthreads();

        // K tile (single plane)
#pragma unroll
        for (int u = 0; u < 4; u++) {
            int idx = u * 256 + tid;
            int r = idx >> 4, c = idx & 15;
            cp_async16(s0 + AKH + r * SKB + c * 16, kh_g + (size_t)r * DIM + c * 8);
        }
        CP_COMMIT();

        // V tile transposed (single plane)
#pragma unroll
        for (int u = 0; u < 4; u++) {
            int idx = u * 256 + tid;
            int kv = idx & 63, c = idx >> 6;
            uint4 xh = *(const uint4*)(vh_g + (size_t)kv * DIM + c * 8);
            const uint16_t* uh = (const uint16_t*)&xh;
#pragma unroll
            for (int j = 0; j < 8; j++)
                *(uint16_t*)(smem + AVT + (c * 8 + j) * SVB + kv * 2) = uh[j];
        }
        CP_WAIT(0);
        __syncthreads();

        // ---- S = Q K^T (2-pass fp16) ----
        float Sa[8][4];
#pragma unroll
        for (int j = 0; j < 8; j++)
#pragma unroll
            for (int q = 0; q < 4; q++) Sa[j][q] = 0.f;

        const uint32_t aBase = s0 + (w * 16 + lrow) * SKB + lkoff;
        const uint32_t kBase = s0 + lrow * SKB + lkoff;
#pragma unroll
        for (int ks = 0; ks < 8; ks++) {
            uint32_t ah[4], al[4];
            ldsm4(ah, aBase + AQH + ks * 32);
            ldsm4(al, aBase + AQL + ks * 32);
#pragma unroll
            for (int p = 0; p < 4; p++) {
                uint32_t kb[4];
                ldsm4(kb, kBase + AKH + p * 16 * SKB + ks * 32);
                mma_f16(Sa[2*p],   ah, kb[0], kb[2]);
                mma_f16(Sa[2*p+1], ah, kb[1], kb[3]);
                mma_f16(Sa[2*p],   al, kb[0], kb[2]);
                mma_f16(Sa[2*p+1], al, kb[1], kb[3]);
            }
        }

        // ---- scale + causal mask ----
        const int r0g = q0 + w * 16 + grp;
        const int r1g = r0g + 8;
        const bool need_mask = (kt >= 2 * qt);
#pragma unroll
        for (int j = 0; j < 8; j++) {
            const int c0 = kv0 + j * 8 + tig * 2;
            Sa[j][0] *= scale; Sa[j][1] *= scale;
            Sa[j][2] *= scale; Sa[j][3] *= scale;
            if (need_mask) {
                if (c0     > r0g) Sa[j][0] = -1e9f;
                if (c0 + 1 > r0g) Sa[j][1] = -1e9f;
                if (c0     > r1g) Sa[j][2] = -1e9f;
                if (c0 + 1 > r1g) Sa[j][3] = -1e9f;
            }
        }

        // ---- online softmax ----
        float mx0 = -1e30f, mx1 = -1e30f;
#pragma unroll
        for (int j = 0; j < 8; j++) {
            mx0 = fmaxf(mx0, fmaxf(Sa[j][0], Sa[j][1]));
            mx1 = fmaxf(mx1, fmaxf(Sa[j][2], Sa[j][3]));
        }
        mx0 = fmaxf(mx0, __shfl_xor_sync(0xffffffff, mx0, 1));
        mx0 = fmaxf(mx0, __shfl_xor_sync(0xffffffff, mx0, 2));
        mx1 = fmaxf(mx1, __shfl_xor_sync(0xffffffff, mx1, 1));
        mx1 = fmaxf(mx1, __shfl_xor_sync(0xffffffff, mx1, 2));

        const float mn0 = fmaxf(m[0], mx0);
        const float mn1 = fmaxf(m[1], mx1);
        const float alpha0 = __expf(m[0] - mn0);
        const float alpha1 = __expf(m[1] - mn1);
        m[0] = mn0; m[1] = mn1;

        float sum0 = 0.f, sum1 = 0.f;
#pragma unroll
        for (int j = 0; j < 8; j++) {
            Sa[j][0] = __expf(Sa[j][0] - mn0);
            Sa[j][1] = __expf(Sa[j][1] - mn0);
            Sa[j][2] = __expf(Sa[j][2] - mn1);
            Sa[j][3] = __expf(Sa[j][3] - mn1);
            sum0 += Sa[j][0] + Sa[j][1];
            sum1 += Sa[j][2] + Sa[j][3];
        }
        sum0 += __shfl_xor_sync(0xffffffff, sum0, 1);
        sum0 += __shfl_xor_sync(0xffffffff, sum0, 2);
        sum1 += __shfl_xor_sync(0xffffffff, sum1, 1);
        sum1 += __shfl_xor_sync(0xffffffff, sum1, 2);
        l[0] = l[0] * alpha0 + sum0;
        l[1] = l[1] * alpha1 + sum1;

#pragma unroll
        for (int nt = 0; nt < 16; nt++) {
            Oa[nt][0] *= alpha0; Oa[nt][1] *= alpha0;
            Oa[nt][2] *= alpha1; Oa[nt][3] *= alpha1;
        }

        // ---- P V (2-pass fp16), P split hi/lo in registers ----
        const uint32_t vBase = s0 + lrow * SVB + lkoff;
#pragma unroll
        for (int ks = 0; ks < 4; ks++) {
            uint32_t ph[4], pl[4];
#pragma unroll
            for (int hf = 0; hf < 2; hf++) {
                const int j = 2 * ks + hf;
                __half2 h01 = __floats2half2_rn(Sa[j][0], Sa[j][1]);
                __half2 h23 = __floats2half2_rn(Sa[j][2], Sa[j][3]);
                ph[2*hf]     = *(uint32_t*)&h01;
                ph[2*hf + 1] = *(uint32_t*)&h23;
                __half2 l01 = __floats2half2_rn(Sa[j][0] - __half2float(h01.x),
                                                Sa[j][1] - __half2float(h01.y));
                __half2 l23 = __floats2half2_rn(Sa[j][2] - __half2float(h23.x),
                                                Sa[j][3] - __half2float(h23.y));
                pl[2*hf]     = *(uint32_t*)&l01;
                pl[2*hf + 1] = *(uint32_t*)&l23;
            }
#pragma unroll
            for (int nb = 0; nb < 8; nb++) {
                uint32_t vb[4];
                ldsm4(vb, vBase + AVT + nb * 16 * SVB + ks * 32);
                mma_f16(Oa[2*nb],   ph, vb[0], vb[2]);
                mma_f16(Oa[2*nb+1], ph, vb[1], vb[3]);
                mma_f16(Oa[2*nb],   pl, vb[0], vb[2]);
                mma_f16(Oa[2*nb+1], pl, vb[1], vb[3]);
            }
        }
    }

    // ---- epilogue: normalize, write fp16 hi/lo planes ----
    const float invl0 = 1.f / l[0];
    const float invl1 = 1.f / l[1];
    const int r0g = q0 + w * 16 + grp;
    const size_t row0 = (size_t)(b * SEQ + r0g) * DIM + h * HD;
    const size_t row1 = row0 + (size_t)8 * DIM;
#pragma unroll
    for (int nt = 0; nt < 16; nt++) {
        const int col = nt * 8 + tig * 2;
        float o0 = Oa[nt][0] * invl0, o1 = Oa[nt][1] * invl0;
        float o2 = Oa[nt][2] * invl1, o3 = Oa[nt][3] * invl1;
        __half2 h01 = __floats2half2_rn(o0, o1);
        __half2 h23 = __floats2half2_rn(o2, o3);
        *(__half2*)(Ohi + row0 + col) = h01;
        *(__half2*)(Ohi + row1 + col) = h23;
        __half2 l01 = __floats2half2_rn(o0 - __half2float(h01.x),
                                        o1 - __half2float(h01.y));
        __half2 l23 = __floats2half2_rn(o2 - __half2float(h23.x),
                                        o3 - __half2float(h23.y));
        *(__half2*)(Olo + row0 + col) = l01;
        *(__half2*)(Olo + row1 + col) = l23;
    }
}

// ---------------------------------------------------------------------------
extern "C" void kernel_launch(void* const* d_in, const int* in_sizes, int n_in,
                              void* d_out, int out_size)
{
    (void)in_sizes; (void)n_in; (void)out_size;
    const float* x  = (const float*)d_in[0];
    const float* Wq = (const float*)d_in[1];
    const float* Wk = (const float*)d_in[2];
    const float* Wv = (const float*)d_in[3];
    const float* Wo = (const float*)d_in[4];
    const float* bo = (const float*)d_in[5];
    float* out = (float*)d_out;

    float *q, *k, *v;
    __half *xh, *xl, *ah, *al, *w16, *qh, *ql, *kh, *vh;
    cudaGetSymbolAddress((void**)&q,   g_q);
    cudaGetSymbolAddress((void**)&k,   g_k);
    cudaGetSymbolAddress((void**)&v,   g_v);
    cudaGetSymbolAddress((void**)&xh,  g_xh);
    cudaGetSymbolAddress((void**)&xl,  g_xl);
    cudaGetSymbolAddress((void**)&ah,  g_ah);
    cudaGetSymbolAddress((void**)&al,  g_al);
    cudaGetSymbolAddress((void**)&w16, g_w16);
    cudaGetSymbolAddress((void**)&qh,  g_qh);
    cudaGetSymbolAddress((void**)&ql,  g_ql);
    cudaGetSymbolAddress((void**)&kh,  g_kh);
    cudaGetSymbolAddress((void**)&vh,  g_vh);

    const size_t WSZ = (size_t)DIM * DIM;
    const int nx4 = (MROWS * DIM) / 4;
    const int nw4 = (DIM * DIM) / 4;

    split16_kernel<<<nx4 / 256, 256>>>(x, xh, xl, nx4);
    cvt16_kernel<<<nw4 / 256, 256>>>(Wq, w16 + 0 * WSZ, nw4);
    cvt16_kernel<<<nw4 / 256, 256>>>(Wk, w16 + 1 * WSZ, nw4);
    cvt16_kernel<<<nw4 / 256, 256>>>(Wv, w16 + 2 * WSZ, nw4);
    cvt16_kernel<<<nw4 / 256, 256>>>(Wo, w16 + 3 * WSZ, nw4);

    cudaFuncSetAttribute(gemm_mma_kernel,
                         cudaFuncAttributeMaxDynamicSharedMemorySize, GSMEM);

    dim3 ggrid(DIM / 128, MROWS / 128);
    gemm_mma_kernel<<<ggrid, 256, GSMEM>>>(xh, xl, w16 + 0 * WSZ, nullptr, q, MROWS, DIM, DIM);
    gemm_mma_kernel<<<ggrid, 256, GSMEM>>>(xh, xl, w16 + 1 * WSZ, nullptr, k, MROWS, DIM, DIM);
    gemm_mma_kernel<<<ggrid, 256, GSMEM>>>(xh, xl, w16 + 2 * WSZ, nullptr, v, MROWS, DIM, DIM);

    int rope_threads = BATCH * SEQ * NHEAD * 64;
    rope_split16_kernel<<<rope_threads / 256, 256>>>(q, qh, ql);
    rope_cvt16_kernel<<<rope_threads / 256, 256>>>(k, kh);
    cvt16_kernel<<<nx4 / 256, 256>>>(v, vh, nx4);

    cudaFuncSetAttribute(attn_mma_kernel,
                         cudaFuncAttributeMaxDynamicSharedMemorySize, ASMEM);
    attn_mma_kernel<<<dim3(SEQ / 128, BATCH * NHEAD), 256, ASMEM>>>(
        qh, ql, kh, vh, ah, al);

    gemm_mma_kernel<<<ggrid, 256, GSMEM>>>(ah, al, w16 + 3 * WSZ, bo, out, MROWS, DIM, DIM);
}